// round 7
// baseline (speedup 1.0000x reference)
#include <cuda_runtime.h>
#include <math.h>

#define NN 512
#define CS 384
#define CZ 128
#define NH 16
#define HD 24
#define EPS 1e-5f
#define ZST 132   // padded z row stride in floats; 16B-aligned, (ZST/4)%8==1 -> LDS.128 conflict-free

// attn smem: ks(512*25) + vs(512*25) + qs(32*25) + wbuf(16*24) floats
#define ATTN_SMEM_FLOATS (512 * 25 * 2 + 32 * 25 + 16 * 24)
#define ATTN_SMEM_BYTES  (ATTN_SMEM_FLOATS * 4)   // 107136

// ---------------- scratch ----------------
__device__ float g_an[NN * CS];
__device__ float g_qkvg[NN * 4 * CS];          // [q(pre-scaled) | k | v | g(sigmoid)]
__device__ float g_bias[(size_t)NH * NN * NN]; // [h][i][j]
__device__ float g_att[NN * CS];
__device__ float g_gwT[NH * CZ];
__device__ float g_colsum[NH];
__device__ float g_cconst[NH];

// ---------------- K0: fold LN(z) constants into Wz ----------------
__global__ void prep_kernel(const float* __restrict__ gz, const float* __restrict__ bzln,
                            const float* __restrict__ Wz, const float* __restrict__ bz) {
    int c = threadIdx.x;  // 128
    float g = gz[c];
    #pragma unroll
    for (int h = 0; h < NH; h++) g_gwT[h * CZ + c] = g * Wz[c * NH + h];
    __syncthreads();
    if (c < NH) {
        float cs = 0.f, ct = bz[c];
        for (int k = 0; k < CZ; k++) {
            cs += g_gwT[c * CZ + k];
            ct += bzln[k] * Wz[k * NH + c];
        }
        g_colsum[c] = cs;
        g_cconst[c] = ct;
    }
}

// ---------------- K1: LN(a) ----------------
__global__ void ln_a_kernel(const float* __restrict__ a, const float* __restrict__ ga,
                            const float* __restrict__ ba) {
    int row = blockIdx.x, t = threadIdx.x;  // 128 threads
    const float* x = a + row * CS;
    float v0 = x[t], v1 = x[t + 128], v2 = x[t + 256];
    float s = v0 + v1 + v2;
    float q = v0 * v0 + v1 * v1 + v2 * v2;
    __shared__ float rs[4], rq[4];
    #pragma unroll
    for (int o = 16; o > 0; o >>= 1) {
        s += __shfl_xor_sync(0xFFFFFFFFu, s, o);
        q += __shfl_xor_sync(0xFFFFFFFFu, q, o);
    }
    if ((t & 31) == 0) { rs[t >> 5] = s; rq[t >> 5] = q; }
    __syncthreads();
    float S = rs[0] + rs[1] + rs[2] + rs[3];
    float Q = rq[0] + rq[1] + rq[2] + rq[3];
    float m = S * (1.f / CS);
    float var = Q * (1.f / CS) - m * m;
    float r = rsqrtf(var + EPS);
    float* o = g_an + row * CS;
    o[t]       = (v0 - m) * r * ga[t]       + ba[t];
    o[t + 128] = (v1 - m) * r * ga[t + 128] + ba[t + 128];
    o[t + 256] = (v2 - m) * r * ga[t + 256] + ba[t + 256];
}

// ---------------- K2: fused QKVG GEMMs ----------------
__global__ void qkvg_kernel(const float* __restrict__ Wq, const float* __restrict__ Wk,
                            const float* __restrict__ Wv, const float* __restrict__ Wg,
                            const float* __restrict__ bg) {
    __shared__ float As[16][64];
    __shared__ float Bs[16][68];
    int mat = blockIdx.z;
    const float* B = (mat == 0) ? Wq : (mat == 1) ? Wk : (mat == 2) ? Wv : Wg;
    int bm = blockIdx.y * 64, bn = blockIdx.x * 64;
    int tid = threadIdx.x;        // 256
    int tx = tid & 15, ty = tid >> 4;
    int arow = tid >> 2, acol4 = (tid & 3) * 4;
    int brow = tid >> 4, bcol4 = (tid & 15) * 4;
    float acc[4][4] = {};

    for (int k0 = 0; k0 < CS; k0 += 16) {
        float4 av = *(const float4*)(g_an + (bm + arow) * CS + k0 + acol4);
        As[acol4 + 0][arow] = av.x;
        As[acol4 + 1][arow] = av.y;
        As[acol4 + 2][arow] = av.z;
        As[acol4 + 3][arow] = av.w;
        float4 bv = *(const float4*)(B + (k0 + brow) * CS + bn + bcol4);
        *(float4*)&Bs[brow][bcol4] = bv;
        __syncthreads();
        #pragma unroll
        for (int kk = 0; kk < 16; kk++) {
            float4 a4 = *(const float4*)&As[kk][ty * 4];
            float4 b4 = *(const float4*)&Bs[kk][tx * 4];
            float af[4] = {a4.x, a4.y, a4.z, a4.w};
            float bf[4] = {b4.x, b4.y, b4.z, b4.w};
            #pragma unroll
            for (int i = 0; i < 4; i++)
                #pragma unroll
                for (int j = 0; j < 4; j++)
                    acc[i][j] += af[i] * bf[j];
        }
        __syncthreads();
    }
    int colbase = mat * CS + bn + tx * 4;
    #pragma unroll
    for (int i = 0; i < 4; i++) {
        int row = bm + ty * 4 + i;
        float* out = g_qkvg + row * (4 * CS) + colbase;
        #pragma unroll
        for (int j = 0; j < 4; j++) {
            float v = acc[i][j];
            if (mat == 0) v *= 0.2041241452319315f;  // 1/sqrt(24)
            else if (mat == 3) v = 1.f / (1.f + __expf(-(v + bg[bn + tx * 4 + j])));
            out[j] = v;
        }
    }
}

// ---------------- K3: fused LN(z) + pair-bias, 4j x 4h register tile ----------------
// grid (4, 512): y = i, x = 128-wide j tile. 128 threads. smem 76800B (2 blocks/SM).
__global__ void __launch_bounds__(128) pair_bias_kernel(const float* __restrict__ z) {
    extern __shared__ float smem[];
    float* zs    = smem;                 // 128 rows x ZST(132)
    float* ws    = zs + 128 * ZST;       // 16 x 128 (gwT)
    float* smean = ws + NH * CZ;         // 128
    float* srstd = smean + 128;          // 128
    __shared__ float cs_s[NH], cc_s[NH];

    int i  = blockIdx.y;
    int j0 = blockIdx.x * 128;
    int t = threadIdx.x;                 // 128
    int lane = t & 31, warp = t >> 5;

    #pragma unroll
    for (int k = 0; k < NH * CZ / 128; k++) ws[t + 128 * k] = g_gwT[t + 128 * k];
    if (t < NH) { cs_s[t] = g_colsum[t]; cc_s[t] = g_cconst[t]; }

    // stage z tile [128 j][128 c] — contiguous 64KB, coalesced float4 copy
    const float4* src = (const float4*)(z + ((size_t)i * NN + j0) * CZ);
    #pragma unroll
    for (int k = 0; k < 32; k++) {
        int idx = t + 128 * k;           // 0..4095
        int row = idx >> 5, c4 = idx & 31;
        *(float4*)(zs + row * ZST + c4 * 4) = src[idx];
    }
    __syncthreads();

    // stats: one row per thread, 4-way ILP
    {
        const float* zr = zs + t * ZST;
        float s0 = 0, s1 = 0, s2 = 0, s3 = 0;
        float q0 = 0, q1 = 0, q2 = 0, q3 = 0;
        #pragma unroll 8
        for (int c = 0; c < CZ; c += 4) {
            float4 v = *(const float4*)(zr + c);
            s0 += v.x; s1 += v.y; s2 += v.z; s3 += v.w;
            q0 += v.x * v.x; q1 += v.y * v.y; q2 += v.z * v.z; q3 += v.w * v.w;
        }
        float s = (s0 + s1) + (s2 + s3);
        float q = (q0 + q1) + (q2 + q3);
        float m = s * (1.f / 128.f);
        float var = q * (1.f / 128.f) - m * m;
        smean[t] = m;
        srstd[t] = rsqrtf(var + EPS);
    }
    __syncthreads();

    // compute: 4 rows x 4 heads per thread, 16 independent accumulators
    const float* z0 = zs + (lane +  0) * ZST;
    const float* z1 = zs + (lane + 32) * ZST;
    const float* z2 = zs + (lane + 64) * ZST;
    const float* z3 = zs + (lane + 96) * ZST;
    const float* w0 = ws + (warp * 4 + 0) * CZ;
    const float* w1 = ws + (warp * 4 + 1) * CZ;
    const float* w2 = ws + (warp * 4 + 2) * CZ;
    const float* w3 = ws + (warp * 4 + 3) * CZ;
    float acc[4][4] = {};
    #pragma unroll 4
    for (int c = 0; c < CZ; c += 4) {
        float4 zv0 = *(const float4*)(z0 + c);
        float4 zv1 = *(const float4*)(z1 + c);
        float4 zv2 = *(const float4*)(z2 + c);
        float4 zv3 = *(const float4*)(z3 + c);
        float4 wv0 = *(const float4*)(w0 + c);
        float4 wv1 = *(const float4*)(w1 + c);
        float4 wv2 = *(const float4*)(w2 + c);
        float4 wv3 = *(const float4*)(w3 + c);
        float zr[4][4] = {{zv0.x, zv0.y, zv0.z, zv0.w},
                          {zv1.x, zv1.y, zv1.z, zv1.w},
                          {zv2.x, zv2.y, zv2.z, zv2.w},
                          {zv3.x, zv3.y, zv3.z, zv3.w}};
        float wr[4][4] = {{wv0.x, wv0.y, wv0.z, wv0.w},
                          {wv1.x, wv1.y, wv1.z, wv1.w},
                          {wv2.x, wv2.y, wv2.z, wv2.w},
                          {wv3.x, wv3.y, wv3.z, wv3.w}};
        #pragma unroll
        for (int r = 0; r < 4; r++)
            #pragma unroll
            for (int h = 0; h < 4; h++)
                acc[r][h] += zr[r][0] * wr[h][0] + zr[r][1] * wr[h][1]
                           + zr[r][2] * wr[h][2] + zr[r][3] * wr[h][3];
    }
    #pragma unroll
    for (int rr = 0; rr < 4; rr++) {
        int row = lane + rr * 32;
        float m = smean[row], r = srstd[row];
        #pragma unroll
        for (int hh = 0; hh < 4; hh++) {
            int h = warp * 4 + hh;
            g_bias[((size_t)h * NN + i) * NN + j0 + row] =
                r * (acc[rr][hh] - m * cs_s[h]) + cc_s[h];
        }
    }
}

// ---------------- K4: attention — 512 threads, 2 q-rows per warp ----------------
__global__ void attn_kernel() {
    extern __shared__ float smem[];
    float* ks   = smem;              // 512 x 25
    float* vs   = ks + 512 * 25;     // 512 x 25
    float* qs   = vs + 512 * 25;     // 32 x 25
    float* wbuf = qs + 32 * 25;      // 16 x 24

    int h  = blockIdx.y;
    int q0 = blockIdx.x * 32;
    int tid = threadIdx.x, lane = tid & 31, warp = tid >> 5;  // 512 thr, 16 warps

    for (int idx = tid; idx < 512 * 24; idx += 512) {
        int n = idx / 24, d = idx - n * 24;
        const float* row = g_qkvg + n * (4 * CS);
        ks[n * 25 + d] = row[CS + h * HD + d];
        vs[n * 25 + d] = row[2 * CS + h * HD + d];
    }
    for (int idx = tid; idx < 32 * 24; idx += 512) {
        int n = idx / 24, d = idx - n * 24;
        qs[n * 25 + d] = g_qkvg[(q0 + n) * (4 * CS) + h * HD + d];
    }
    __syncthreads();

    for (int qr = 0; qr < 2; qr++) {
        int qlocal = warp * 2 + qr;
        int qrow = q0 + qlocal;
        const float* qp = qs + qlocal * 25;
        const float* brow = g_bias + ((size_t)h * NN + qrow) * NN;

        float e[16];
        float mx = -1e30f;
        #pragma unroll
        for (int jj = 0; jj < 16; jj++) {
            int j = jj * 32 + lane;
            const float* kp = ks + j * 25;
            float s = 0.f;
            #pragma unroll
            for (int d = 0; d < 24; d++) s += qp[d] * kp[d];
            s += brow[j];
            e[jj] = s;
            mx = fmaxf(mx, s);
        }
        #pragma unroll
        for (int o = 16; o > 0; o >>= 1) mx = fmaxf(mx, __shfl_xor_sync(0xFFFFFFFFu, mx, o));
        float sumv = 0.f;
        #pragma unroll
        for (int jj = 0; jj < 16; jj++) { e[jj] = __expf(e[jj] - mx); sumv += e[jj]; }
        #pragma unroll
        for (int o = 16; o > 0; o >>= 1) sumv += __shfl_xor_sync(0xFFFFFFFFu, sumv, o);
        float inv = 1.f / sumv;

        float acc[24];
        #pragma unroll
        for (int d = 0; d < 24; d++) acc[d] = 0.f;
        #pragma unroll
        for (int jj = 0; jj < 16; jj++) {
            int j = jj * 32 + lane;
            const float* vp = vs + j * 25;
            float p = e[jj];
            #pragma unroll
            for (int d = 0; d < 24; d++) acc[d] += p * vp[d];
        }
        float* wb = wbuf + warp * 24;
        #pragma unroll
        for (int d = 0; d < 24; d++) {
            float v = acc[d];
            v += __shfl_xor_sync(0xFFFFFFFFu, v, 16);
            v += __shfl_xor_sync(0xFFFFFFFFu, v, 8);
            v += __shfl_xor_sync(0xFFFFFFFFu, v, 4);
            v += __shfl_xor_sync(0xFFFFFFFFu, v, 2);
            v += __shfl_xor_sync(0xFFFFFFFFu, v, 1);
            if (lane == 0) wb[d] = v;
        }
        __syncwarp();
        if (lane < 24) {
            float ov = wb[lane] * inv;
            float gv = g_qkvg[qrow * (4 * CS) + 3 * CS + h * HD + lane];
            g_att[qrow * CS + h * HD + lane] = ov * gv;
        }
        __syncwarp();
    }
}

// ---------------- K5: output projection ----------------
__global__ void outproj_kernel(const float* __restrict__ Wo, const float* __restrict__ bo,
                               float* __restrict__ out) {
    __shared__ float As[16][64];
    __shared__ float Bs[16][68];
    int bm = blockIdx.y * 64, bn = blockIdx.x * 64;
    int tid = threadIdx.x;
    int tx = tid & 15, ty = tid >> 4;
    int arow = tid >> 2, acol4 = (tid & 3) * 4;
    int brow = tid >> 4, bcol4 = (tid & 15) * 4;
    float acc[4][4] = {};

    for (int k0 = 0; k0 < CS; k0 += 16) {
        float4 av = *(const float4*)(g_att + (bm + arow) * CS + k0 + acol4);
        As[acol4 + 0][arow] = av.x;
        As[acol4 + 1][arow] = av.y;
        As[acol4 + 2][arow] = av.z;
        As[acol4 + 3][arow] = av.w;
        float4 bv = *(const float4*)(Wo + (k0 + brow) * CS + bn + bcol4);
        *(float4*)&Bs[brow][bcol4] = bv;
        __syncthreads();
        #pragma unroll
        for (int kk = 0; kk < 16; kk++) {
            float4 a4 = *(const float4*)&As[kk][ty * 4];
            float4 b4 = *(const float4*)&Bs[kk][tx * 4];
            float af[4] = {a4.x, a4.y, a4.z, a4.w};
            float bf[4] = {b4.x, b4.y, b4.z, b4.w};
            #pragma unroll
            for (int i = 0; i < 4; i++)
                #pragma unroll
                for (int j = 0; j < 4; j++)
                    acc[i][j] += af[i] * bf[j];
        }
        __syncthreads();
    }
    #pragma unroll
    for (int i = 0; i < 4; i++) {
        int row = bm + ty * 4 + i;
        float* o = out + row * CS + bn + tx * 4;
        #pragma unroll
        for (int j = 0; j < 4; j++)
            o[j] = acc[i][j] + bo[bn + tx * 4 + j];
    }
}

// ---------------- launch ----------------
extern "C" void kernel_launch(void* const* d_in, const int* in_sizes, int n_in,
                              void* d_out, int out_size) {
    (void)in_sizes; (void)n_in; (void)out_size;
    const float* a   = (const float*)d_in[0];
    const float* z   = (const float*)d_in[1];
    const float* g_a = (const float*)d_in[2];
    const float* b_a = (const float*)d_in[3];
    const float* g_z = (const float*)d_in[4];
    const float* b_z = (const float*)d_in[5];
    const float* Wz  = (const float*)d_in[6];
    const float* bz  = (const float*)d_in[7];
    const float* Wq  = (const float*)d_in[8];
    const float* Wk  = (const float*)d_in[9];
    const float* Wv  = (const float*)d_in[10];
    const float* Wg  = (const float*)d_in[11];
    const float* bg  = (const float*)d_in[12];
    const float* Wo  = (const float*)d_in[13];
    const float* bo  = (const float*)d_in[14];
    float* out = (float*)d_out;

    const int PB_SMEM = (128 * ZST + NH * CZ + 128 + 128) * 4;  // 76800 B
    cudaFuncSetAttribute(pair_bias_kernel, cudaFuncAttributeMaxDynamicSharedMemorySize, PB_SMEM);
    cudaFuncSetAttribute(attn_kernel, cudaFuncAttributeMaxDynamicSharedMemorySize, ATTN_SMEM_BYTES);

    prep_kernel<<<1, 128>>>(g_z, b_z, Wz, bz);
    ln_a_kernel<<<NN, 128>>>(a, g_a, b_a);
    qkvg_kernel<<<dim3(6, 8, 4), 256>>>(Wq, Wk, Wv, Wg, bg);
    pair_bias_kernel<<<dim3(4, NN), 128, PB_SMEM>>>(z);
    attn_kernel<<<dim3(16, 16), 512, ATTN_SMEM_BYTES>>>();
    outproj_kernel<<<dim3(6, 8), 256>>>(Wo, bo, out);
}

// round 8
// speedup vs baseline: 1.0954x; 1.0954x over previous
#include <cuda_runtime.h>
#include <math.h>

#define NN 512
#define CS 384
#define CZ 128
#define NH 16
#define HD 24
#define EPS 1e-5f
#define ZST 132   // padded z row stride in floats; 16B-aligned, (ZST/4)%8==1 -> LDS.128 conflict-free

// pair_bias smem layout (floats)
#define PB_ZS     (128 * ZST)              // 16896
#define PB_WS     (NH * CZ)                // 2048
#define PB_STATS  (256)                    // smean+srstd
#define PB_PART   (4 * 32 * 17)            // 2176 (padded partials)
#define PB_SMEM_FLOATS (PB_ZS + PB_WS + PB_STATS + PB_PART)
#define PB_SMEM_BYTES  (PB_SMEM_FLOATS * 4)   // 85504

// ---------------- scratch ----------------
__device__ float g_an[NN * CS];
__device__ float g_qkvg[NN * 4 * CS];          // [q(pre-scaled) | k | v | g(sigmoid)]
__device__ float g_bias[(size_t)NH * NN * NN]; // [h][i][j]
__device__ float g_att[NN * CS];
__device__ float g_gwT[NH * CZ];
__device__ float g_colsum[NH];
__device__ float g_cconst[NH];

// ---------------- K0: fold LN(z) constants into Wz ----------------
__global__ void prep_kernel(const float* __restrict__ gz, const float* __restrict__ bzln,
                            const float* __restrict__ Wz, const float* __restrict__ bz) {
    int c = threadIdx.x;  // 128
    float g = gz[c];
    #pragma unroll
    for (int h = 0; h < NH; h++) g_gwT[h * CZ + c] = g * Wz[c * NH + h];
    __syncthreads();
    if (c < NH) {
        float cs = 0.f, ct = bz[c];
        for (int k = 0; k < CZ; k++) {
            cs += g_gwT[c * CZ + k];
            ct += bzln[k] * Wz[k * NH + c];
        }
        g_colsum[c] = cs;
        g_cconst[c] = ct;
    }
}

// ---------------- K1: LN(a) ----------------
__global__ void ln_a_kernel(const float* __restrict__ a, const float* __restrict__ ga,
                            const float* __restrict__ ba) {
    int row = blockIdx.x, t = threadIdx.x;  // 128 threads
    const float* x = a + row * CS;
    float v0 = x[t], v1 = x[t + 128], v2 = x[t + 256];
    float s = v0 + v1 + v2;
    float q = v0 * v0 + v1 * v1 + v2 * v2;
    __shared__ float rs[4], rq[4];
    #pragma unroll
    for (int o = 16; o > 0; o >>= 1) {
        s += __shfl_xor_sync(0xFFFFFFFFu, s, o);
        q += __shfl_xor_sync(0xFFFFFFFFu, q, o);
    }
    if ((t & 31) == 0) { rs[t >> 5] = s; rq[t >> 5] = q; }
    __syncthreads();
    float S = rs[0] + rs[1] + rs[2] + rs[3];
    float Q = rq[0] + rq[1] + rq[2] + rq[3];
    float m = S * (1.f / CS);
    float var = Q * (1.f / CS) - m * m;
    float r = rsqrtf(var + EPS);
    float* o = g_an + row * CS;
    o[t]       = (v0 - m) * r * ga[t]       + ba[t];
    o[t + 128] = (v1 - m) * r * ga[t + 128] + ba[t + 128];
    o[t + 256] = (v2 - m) * r * ga[t + 256] + ba[t + 256];
}

// ---------------- K2: fused QKVG GEMMs ----------------
__global__ void qkvg_kernel(const float* __restrict__ Wq, const float* __restrict__ Wk,
                            const float* __restrict__ Wv, const float* __restrict__ Wg,
                            const float* __restrict__ bg) {
    __shared__ float As[16][64];
    __shared__ float Bs[16][68];
    int mat = blockIdx.z;
    const float* B = (mat == 0) ? Wq : (mat == 1) ? Wk : (mat == 2) ? Wv : Wg;
    int bm = blockIdx.y * 64, bn = blockIdx.x * 64;
    int tid = threadIdx.x;        // 256
    int tx = tid & 15, ty = tid >> 4;
    int arow = tid >> 2, acol4 = (tid & 3) * 4;
    int brow = tid >> 4, bcol4 = (tid & 15) * 4;
    float acc[4][4] = {};

    for (int k0 = 0; k0 < CS; k0 += 16) {
        float4 av = *(const float4*)(g_an + (bm + arow) * CS + k0 + acol4);
        As[acol4 + 0][arow] = av.x;
        As[acol4 + 1][arow] = av.y;
        As[acol4 + 2][arow] = av.z;
        As[acol4 + 3][arow] = av.w;
        float4 bv = *(const float4*)(B + (k0 + brow) * CS + bn + bcol4);
        *(float4*)&Bs[brow][bcol4] = bv;
        __syncthreads();
        #pragma unroll
        for (int kk = 0; kk < 16; kk++) {
            float4 a4 = *(const float4*)&As[kk][ty * 4];
            float4 b4 = *(const float4*)&Bs[kk][tx * 4];
            float af[4] = {a4.x, a4.y, a4.z, a4.w};
            float bf[4] = {b4.x, b4.y, b4.z, b4.w};
            #pragma unroll
            for (int i = 0; i < 4; i++)
                #pragma unroll
                for (int j = 0; j < 4; j++)
                    acc[i][j] += af[i] * bf[j];
        }
        __syncthreads();
    }
    int colbase = mat * CS + bn + tx * 4;
    #pragma unroll
    for (int i = 0; i < 4; i++) {
        int row = bm + ty * 4 + i;
        float* out = g_qkvg + row * (4 * CS) + colbase;
        #pragma unroll
        for (int j = 0; j < 4; j++) {
            float v = acc[i][j];
            if (mat == 0) v *= 0.2041241452319315f;  // 1/sqrt(24)
            else if (mat == 3) v = 1.f / (1.f + __expf(-(v + bg[bn + tx * 4 + j])));
            out[j] = v;
        }
    }
}

// ---------------- K3: fused LN(z) + pair-bias, 4j x 4h tile, c-split ----------------
// grid (4, 512): y = i, x = 128-wide j tile. 256 threads, smem 85504B (2 blocks/SM, 16 warps).
// Warp pairs {w, w+4} share output tile (heads 4w..4w+3, rows lane+{0,32,64,96});
// w reduces c[0,64), w+4 reduces c[64,128); partials combined via padded smem.
__global__ void __launch_bounds__(256) pair_bias_kernel(const float* __restrict__ z) {
    extern __shared__ float smem[];
    float* zs    = smem;                 // 128 x ZST
    float* ws    = zs + PB_ZS;           // 16 x 128
    float* smean = ws + PB_WS;           // 128
    float* srstd = smean + 128;          // 128
    float* part  = srstd + 128;          // [4 hq][32 lane][17]
    __shared__ float cs_s[NH], cc_s[NH];

    int i  = blockIdx.y;
    int j0 = blockIdx.x * 128;
    int t = threadIdx.x;                 // 256
    int lane = t & 31, warp = t >> 5;    // 8 warps

    // stage weights (2048 floats) + constants
    #pragma unroll
    for (int k = 0; k < PB_WS / 256; k++) ws[t + 256 * k] = g_gwT[t + 256 * k];
    if (t < NH) { cs_s[t] = g_colsum[t]; cc_s[t] = g_cconst[t]; }

    // stage z tile [128 j][128 c] — contiguous 64KB, coalesced float4 copy
    const float4* src = (const float4*)(z + ((size_t)i * NN + j0) * CZ);
    #pragma unroll
    for (int k = 0; k < 16; k++) {
        int idx = t + 256 * k;           // 0..4095
        int row = idx >> 5, c4 = idx & 31;
        *(float4*)(zs + row * ZST + c4 * 4) = src[idx];
    }
    __syncthreads();

    // stats: thread t -> row t>>1, c-half t&1 (64 c each), combine via shuffle
    {
        int row = t >> 1, half = t & 1;
        const float* zr = zs + row * ZST + half * 64;
        float s0 = 0, s1 = 0, s2 = 0, s3 = 0;
        float q0 = 0, q1 = 0, q2 = 0, q3 = 0;
        #pragma unroll
        for (int c = 0; c < 64; c += 4) {
            float4 v = *(const float4*)(zr + c);
            s0 += v.x; s1 += v.y; s2 += v.z; s3 += v.w;
            q0 += v.x * v.x; q1 += v.y * v.y; q2 += v.z * v.z; q3 += v.w * v.w;
        }
        float s = (s0 + s1) + (s2 + s3);
        float q = (q0 + q1) + (q2 + q3);
        s += __shfl_xor_sync(0xFFFFFFFFu, s, 1);
        q += __shfl_xor_sync(0xFFFFFFFFu, q, 1);
        if (half == 0) {
            float m = s * (1.f / 128.f);
            float var = q * (1.f / 128.f) - m * m;
            smean[row] = m;
            srstd[row] = rsqrtf(var + EPS);
        }
    }
    __syncthreads();

    // compute: 4 rows x 4 heads per thread over this warp's 64-c half
    int hq = warp & 3;                   // head quad 0..3
    int cbase = (warp >> 2) * 64;        // 0 or 64
    const float* z0 = zs + (lane +  0) * ZST + cbase;
    const float* z1 = zs + (lane + 32) * ZST + cbase;
    const float* z2 = zs + (lane + 64) * ZST + cbase;
    const float* z3 = zs + (lane + 96) * ZST + cbase;
    const float* w0 = ws + (hq * 4 + 0) * CZ + cbase;
    const float* w1 = ws + (hq * 4 + 1) * CZ + cbase;
    const float* w2 = ws + (hq * 4 + 2) * CZ + cbase;
    const float* w3 = ws + (hq * 4 + 3) * CZ + cbase;
    float acc[4][4] = {};
    #pragma unroll 4
    for (int c = 0; c < 64; c += 4) {
        float4 zv0 = *(const float4*)(z0 + c);
        float4 zv1 = *(const float4*)(z1 + c);
        float4 zv2 = *(const float4*)(z2 + c);
        float4 zv3 = *(const float4*)(z3 + c);
        float4 wv0 = *(const float4*)(w0 + c);
        float4 wv1 = *(const float4*)(w1 + c);
        float4 wv2 = *(const float4*)(w2 + c);
        float4 wv3 = *(const float4*)(w3 + c);
        float zr[4][4] = {{zv0.x, zv0.y, zv0.z, zv0.w},
                          {zv1.x, zv1.y, zv1.z, zv1.w},
                          {zv2.x, zv2.y, zv2.z, zv2.w},
                          {zv3.x, zv3.y, zv3.z, zv3.w}};
        float wr[4][4] = {{wv0.x, wv0.y, wv0.z, wv0.w},
                          {wv1.x, wv1.y, wv1.z, wv1.w},
                          {wv2.x, wv2.y, wv2.z, wv2.w},
                          {wv3.x, wv3.y, wv3.z, wv3.w}};
        #pragma unroll
        for (int r = 0; r < 4; r++)
            #pragma unroll
            for (int h = 0; h < 4; h++)
                acc[r][h] += zr[r][0] * wr[h][0] + zr[r][1] * wr[h][1]
                           + zr[r][2] * wr[h][2] + zr[r][3] * wr[h][3];
    }

    // high-c warps publish partials (stride-17 padding -> conflict-free)
    if (warp >= 4) {
        float* p = part + (hq * 32 + lane) * 17;
        #pragma unroll
        for (int r = 0; r < 4; r++)
            #pragma unroll
            for (int h = 0; h < 4; h++)
                p[r * 4 + h] = acc[r][h];
    }
    __syncthreads();
    if (warp < 4) {
        const float* p = part + (hq * 32 + lane) * 17;
        #pragma unroll
        for (int rr = 0; rr < 4; rr++) {
            int row = lane + rr * 32;
            float m = smean[row], r = srstd[row];
            #pragma unroll
            for (int hh = 0; hh < 4; hh++) {
                int h = hq * 4 + hh;
                float v = acc[rr][hh] + p[rr * 4 + hh];
                g_bias[((size_t)h * NN + i) * NN + j0 + row] =
                    r * (v - m * cs_s[h]) + cc_s[h];
            }
        }
    }
}

// ---------------- K4: attention (256 threads, 4 q-rows per warp) ----------------
__global__ void attn_kernel() {
    extern __shared__ float smem[];
    float* ks   = smem;              // 512 x 25
    float* vs   = ks + 512 * 25;     // 512 x 25
    float* qs   = vs + 512 * 25;     // 32 x 25
    float* wbuf = qs + 32 * 25;      // 8 x 24

    int h  = blockIdx.y;
    int q0 = blockIdx.x * 32;
    int tid = threadIdx.x, lane = tid & 31, warp = tid >> 5;

    for (int idx = tid; idx < 512 * 24; idx += 256) {
        int n = idx / 24, d = idx - n * 24;
        const float* row = g_qkvg + n * (4 * CS);
        ks[n * 25 + d] = row[CS + h * HD + d];
        vs[n * 25 + d] = row[2 * CS + h * HD + d];
    }
    for (int idx = tid; idx < 32 * 24; idx += 256) {
        int n = idx / 24, d = idx - n * 24;
        qs[n * 25 + d] = g_qkvg[(q0 + n) * (4 * CS) + h * HD + d];
    }
    __syncthreads();

    for (int qr = 0; qr < 4; qr++) {
        int qlocal = warp * 4 + qr;
        int qrow = q0 + qlocal;
        const float* qp = qs + qlocal * 25;
        const float* brow = g_bias + ((size_t)h * NN + qrow) * NN;

        float e[16];
        float mx = -1e30f;
        #pragma unroll
        for (int jj = 0; jj < 16; jj++) {
            int j = jj * 32 + lane;
            const float* kp = ks + j * 25;
            float s = 0.f;
            #pragma unroll
            for (int d = 0; d < 24; d++) s += qp[d] * kp[d];
            s += brow[j];
            e[jj] = s;
            mx = fmaxf(mx, s);
        }
        #pragma unroll
        for (int o = 16; o > 0; o >>= 1) mx = fmaxf(mx, __shfl_xor_sync(0xFFFFFFFFu, mx, o));
        float sumv = 0.f;
        #pragma unroll
        for (int jj = 0; jj < 16; jj++) { e[jj] = __expf(e[jj] - mx); sumv += e[jj]; }
        #pragma unroll
        for (int o = 16; o > 0; o >>= 1) sumv += __shfl_xor_sync(0xFFFFFFFFu, sumv, o);
        float inv = 1.f / sumv;

        float acc[24];
        #pragma unroll
        for (int d = 0; d < 24; d++) acc[d] = 0.f;
        #pragma unroll
        for (int jj = 0; jj < 16; jj++) {
            int j = jj * 32 + lane;
            const float* vp = vs + j * 25;
            float p = e[jj];
            #pragma unroll
            for (int d = 0; d < 24; d++) acc[d] += p * vp[d];
        }
        float* wb = wbuf + warp * 24;
        #pragma unroll
        for (int d = 0; d < 24; d++) {
            float v = acc[d];
            v += __shfl_xor_sync(0xFFFFFFFFu, v, 16);
            v += __shfl_xor_sync(0xFFFFFFFFu, v, 8);
            v += __shfl_xor_sync(0xFFFFFFFFu, v, 4);
            v += __shfl_xor_sync(0xFFFFFFFFu, v, 2);
            v += __shfl_xor_sync(0xFFFFFFFFu, v, 1);
            if (lane == 0) wb[d] = v;
        }
        __syncwarp();
        if (lane < 24) {
            float ov = wb[lane] * inv;
            float gv = g_qkvg[qrow * (4 * CS) + 3 * CS + h * HD + lane];
            g_att[qrow * CS + h * HD + lane] = ov * gv;
        }
        __syncwarp();
    }
}

// ---------------- K5: output projection ----------------
__global__ void outproj_kernel(const float* __restrict__ Wo, const float* __restrict__ bo,
                               float* __restrict__ out) {
    __shared__ float As[16][64];
    __shared__ float Bs[16][68];
    int bm = blockIdx.y * 64, bn = blockIdx.x * 64;
    int tid = threadIdx.x;
    int tx = tid & 15, ty = tid >> 4;
    int arow = tid >> 2, acol4 = (tid & 3) * 4;
    int brow = tid >> 4, bcol4 = (tid & 15) * 4;
    float acc[4][4] = {};

    for (int k0 = 0; k0 < CS; k0 += 16) {
        float4 av = *(const float4*)(g_att + (bm + arow) * CS + k0 + acol4);
        As[acol4 + 0][arow] = av.x;
        As[acol4 + 1][arow] = av.y;
        As[acol4 + 2][arow] = av.z;
        As[acol4 + 3][arow] = av.w;
        float4 bv = *(const float4*)(Wo + (k0 + brow) * CS + bn + bcol4);
        *(float4*)&Bs[brow][bcol4] = bv;
        __syncthreads();
        #pragma unroll
        for (int kk = 0; kk < 16; kk++) {
            float4 a4 = *(const float4*)&As[kk][ty * 4];
            float4 b4 = *(const float4*)&Bs[kk][tx * 4];
            float af[4] = {a4.x, a4.y, a4.z, a4.w};
            float bf[4] = {b4.x, b4.y, b4.z, b4.w};
            #pragma unroll
            for (int i = 0; i < 4; i++)
                #pragma unroll
                for (int j = 0; j < 4; j++)
                    acc[i][j] += af[i] * bf[j];
        }
        __syncthreads();
    }
    #pragma unroll
    for (int i = 0; i < 4; i++) {
        int row = bm + ty * 4 + i;
        float* o = out + row * CS + bn + tx * 4;
        #pragma unroll
        for (int j = 0; j < 4; j++)
            o[j] = acc[i][j] + bo[bn + tx * 4 + j];
    }
}

// ---------------- launch ----------------
extern "C" void kernel_launch(void* const* d_in, const int* in_sizes, int n_in,
                              void* d_out, int out_size) {
    (void)in_sizes; (void)n_in; (void)out_size;
    const float* a   = (const float*)d_in[0];
    const float* z   = (const float*)d_in[1];
    const float* g_a = (const float*)d_in[2];
    const float* b_a = (const float*)d_in[3];
    const float* g_z = (const float*)d_in[4];
    const float* b_z = (const float*)d_in[5];
    const float* Wz  = (const float*)d_in[6];
    const float* bz  = (const float*)d_in[7];
    const float* Wq  = (const float*)d_in[8];
    const float* Wk  = (const float*)d_in[9];
    const float* Wv  = (const float*)d_in[10];
    const float* Wg  = (const float*)d_in[11];
    const float* bg  = (const float*)d_in[12];
    const float* Wo  = (const float*)d_in[13];
    const float* bo  = (const float*)d_in[14];
    float* out = (float*)d_out;

    const int ATTN_SMEM = (512 * 25 * 2 + 32 * 25 + 8 * 24) * 4;  // 106368
    cudaFuncSetAttribute(pair_bias_kernel, cudaFuncAttributeMaxDynamicSharedMemorySize, PB_SMEM_BYTES);
    cudaFuncSetAttribute(attn_kernel, cudaFuncAttributeMaxDynamicSharedMemorySize, ATTN_SMEM);

    prep_kernel<<<1, 128>>>(g_z, b_z, Wz, bz);
    ln_a_kernel<<<NN, 128>>>(a, g_a, b_a);
    qkvg_kernel<<<dim3(6, 8, 4), 256>>>(Wq, Wk, Wv, Wg, bg);
    pair_bias_kernel<<<dim3(4, NN), 256, PB_SMEM_BYTES>>>(z);
    attn_kernel<<<dim3(16, 16), 256, ATTN_SMEM>>>();
    outproj_kernel<<<dim3(6, 8), 256>>>(Wo, bo, out);
}

// round 10
// speedup vs baseline: 1.1154x; 1.0183x over previous
#include <cuda_runtime.h>
#include <math.h>

#define NN 512
#define CS 384
#define CZ 128
#define NH 16
#define HD 24
#define EPS 1e-5f
#define ZST 132   // padded z row stride; 16B-aligned, (ZST/4)%8==1 -> LDS.128 conflict-free
#define KST 28    // padded K/V row stride; 16B-aligned, 7 mod 8 -> LDS.128 conflict-free

// pair_bias smem layout (floats)
#define PB_ZS     (128 * ZST)
#define PB_WS     (NH * CZ)
#define PB_STATS  (256)
#define PB_PART   (4 * 32 * 17)
#define PB_SMEM_FLOATS (PB_ZS + PB_WS + PB_STATS + PB_PART)
#define PB_SMEM_BYTES  (PB_SMEM_FLOATS * 4)   // 85504

// attn smem: ks(512*28) + vs(512*28) + qs(32*28) + wbuf(8*48)
#define ATTN_SMEM_FLOATS (512 * KST * 2 + 32 * KST + 8 * 48)
#define ATTN_SMEM_BYTES  (ATTN_SMEM_FLOATS * 4)   // 119808

// ---------------- scratch ----------------
__device__ float g_an[NN * CS];
__device__ float g_qkvg[NN * 4 * CS];          // [q(pre-scaled) | k | v | g(sigmoid)]
__device__ float g_bias[(size_t)NH * NN * NN]; // [h][i][j]
__device__ float g_att[NN * CS];
__device__ float g_gwT[NH * CZ];
__device__ float g_colsum[NH];
__device__ float g_cconst[NH];

// ---------------- K0: fold LN(z) constants into Wz ----------------
__global__ void prep_kernel(const float* __restrict__ gz, const float* __restrict__ bzln,
                            const float* __restrict__ Wz, const float* __restrict__ bz) {
    int c = threadIdx.x;  // 128
    float g = gz[c];
    #pragma unroll
    for (int h = 0; h < NH; h++) g_gwT[h * CZ + c] = g * Wz[c * NH + h];
    __syncthreads();
    if (c < NH) {
        float cs = 0.f, ct = bz[c];
        for (int k = 0; k < CZ; k++) {
            cs += g_gwT[c * CZ + k];
            ct += bzln[k] * Wz[k * NH + c];
        }
        g_colsum[c] = cs;
        g_cconst[c] = ct;
    }
}

// ---------------- K1: LN(a) ----------------
__global__ void ln_a_kernel(const float* __restrict__ a, const float* __restrict__ ga,
                            const float* __restrict__ ba) {
    int row = blockIdx.x, t = threadIdx.x;  // 128 threads
    const float* x = a + row * CS;
    float v0 = x[t], v1 = x[t + 128], v2 = x[t + 256];
    float s = v0 + v1 + v2;
    float q = v0 * v0 + v1 * v1 + v2 * v2;
    __shared__ float rs[4], rq[4];
    #pragma unroll
    for (int o = 16; o > 0; o >>= 1) {
        s += __shfl_xor_sync(0xFFFFFFFFu, s, o);
        q += __shfl_xor_sync(0xFFFFFFFFu, q, o);
    }
    if ((t & 31) == 0) { rs[t >> 5] = s; rq[t >> 5] = q; }
    __syncthreads();
    float S = rs[0] + rs[1] + rs[2] + rs[3];
    float Q = rq[0] + rq[1] + rq[2] + rq[3];
    float m = S * (1.f / CS);
    float var = Q * (1.f / CS) - m * m;
    float r = rsqrtf(var + EPS);
    float* o = g_an + row * CS;
    o[t]       = (v0 - m) * r * ga[t]       + ba[t];
    o[t + 128] = (v1 - m) * r * ga[t + 128] + ba[t + 128];
    o[t + 256] = (v2 - m) * r * ga[t + 256] + ba[t + 256];
}

// ---------------- K2: fused QKVG GEMMs ----------------
__global__ void qkvg_kernel(const float* __restrict__ Wq, const float* __restrict__ Wk,
                            const float* __restrict__ Wv, const float* __restrict__ Wg,
                            const float* __restrict__ bg) {
    __shared__ float As[16][64];
    __shared__ float Bs[16][68];
    int mat = blockIdx.z;
    const float* B = (mat == 0) ? Wq : (mat == 1) ? Wk : (mat == 2) ? Wv : Wg;
    int bm = blockIdx.y * 64, bn = blockIdx.x * 64;
    int tid = threadIdx.x;        // 256
    int tx = tid & 15, ty = tid >> 4;
    int arow = tid >> 2, acol4 = (tid & 3) * 4;
    int brow = tid >> 4, bcol4 = (tid & 15) * 4;
    float acc[4][4] = {};

    for (int k0 = 0; k0 < CS; k0 += 16) {
        float4 av = *(const float4*)(g_an + (bm + arow) * CS + k0 + acol4);
        As[acol4 + 0][arow] = av.x;
        As[acol4 + 1][arow] = av.y;
        As[acol4 + 2][arow] = av.z;
        As[acol4 + 3][arow] = av.w;
        float4 bv = *(const float4*)(B + (k0 + brow) * CS + bn + bcol4);
        *(float4*)&Bs[brow][bcol4] = bv;
        __syncthreads();
        #pragma unroll
        for (int kk = 0; kk < 16; kk++) {
            float4 a4 = *(const float4*)&As[kk][ty * 4];
            float4 b4 = *(const float4*)&Bs[kk][tx * 4];
            float af[4] = {a4.x, a4.y, a4.z, a4.w};
            float bf[4] = {b4.x, b4.y, b4.z, b4.w};
            #pragma unroll
            for (int i = 0; i < 4; i++)
                #pragma unroll
                for (int j = 0; j < 4; j++)
                    acc[i][j] += af[i] * bf[j];
        }
        __syncthreads();
    }
    int colbase = mat * CS + bn + tx * 4;
    #pragma unroll
    for (int i = 0; i < 4; i++) {
        int row = bm + ty * 4 + i;
        float* out = g_qkvg + row * (4 * CS) + colbase;
        #pragma unroll
        for (int j = 0; j < 4; j++) {
            float v = acc[i][j];
            if (mat == 0) v *= 0.2041241452319315f;  // 1/sqrt(24)
            else if (mat == 3) v = 1.f / (1.f + __expf(-(v + bg[bn + tx * 4 + j])));
            out[j] = v;
        }
    }
}

// ---------------- K3: fused LN(z) + pair-bias, 4j x 4h tile, c-split ----------------
__global__ void __launch_bounds__(256) pair_bias_kernel(const float* __restrict__ z) {
    extern __shared__ float smem[];
    float* zs    = smem;                 // 128 x ZST
    float* ws    = zs + PB_ZS;           // 16 x 128
    float* smean = ws + PB_WS;           // 128
    float* srstd = smean + 128;          // 128
    float* part  = srstd + 128;          // [4 hq][32 lane][17]
    __shared__ float cs_s[NH], cc_s[NH];

    int i  = blockIdx.y;
    int j0 = blockIdx.x * 128;
    int t = threadIdx.x;                 // 256
    int lane = t & 31, warp = t >> 5;    // 8 warps

    #pragma unroll
    for (int k = 0; k < PB_WS / 256; k++) ws[t + 256 * k] = g_gwT[t + 256 * k];
    if (t < NH) { cs_s[t] = g_colsum[t]; cc_s[t] = g_cconst[t]; }

    const float4* src = (const float4*)(z + ((size_t)i * NN + j0) * CZ);
    #pragma unroll
    for (int k = 0; k < 16; k++) {
        int idx = t + 256 * k;
        int row = idx >> 5, c4 = idx & 31;
        *(float4*)(zs + row * ZST + c4 * 4) = src[idx];
    }
    __syncthreads();

    {
        int row = t >> 1, half = t & 1;
        const float* zr = zs + row * ZST + half * 64;
        float s0 = 0, s1 = 0, s2 = 0, s3 = 0;
        float q0 = 0, q1 = 0, q2 = 0, q3 = 0;
        #pragma unroll
        for (int c = 0; c < 64; c += 4) {
            float4 v = *(const float4*)(zr + c);
            s0 += v.x; s1 += v.y; s2 += v.z; s3 += v.w;
            q0 += v.x * v.x; q1 += v.y * v.y; q2 += v.z * v.z; q3 += v.w * v.w;
        }
        float s = (s0 + s1) + (s2 + s3);
        float q = (q0 + q1) + (q2 + q3);
        s += __shfl_xor_sync(0xFFFFFFFFu, s, 1);
        q += __shfl_xor_sync(0xFFFFFFFFu, q, 1);
        if (half == 0) {
            float m = s * (1.f / 128.f);
            float var = q * (1.f / 128.f) - m * m;
            smean[row] = m;
            srstd[row] = rsqrtf(var + EPS);
        }
    }
    __syncthreads();

    int hq = warp & 3;
    int cbase = (warp >> 2) * 64;
    const float* z0 = zs + (lane +  0) * ZST + cbase;
    const float* z1 = zs + (lane + 32) * ZST + cbase;
    const float* z2 = zs + (lane + 64) * ZST + cbase;
    const float* z3 = zs + (lane + 96) * ZST + cbase;
    const float* w0 = ws + (hq * 4 + 0) * CZ + cbase;
    const float* w1 = ws + (hq * 4 + 1) * CZ + cbase;
    const float* w2 = ws + (hq * 4 + 2) * CZ + cbase;
    const float* w3 = ws + (hq * 4 + 3) * CZ + cbase;
    float acc[4][4] = {};
    #pragma unroll 4
    for (int c = 0; c < 64; c += 4) {
        float4 zv0 = *(const float4*)(z0 + c);
        float4 zv1 = *(const float4*)(z1 + c);
        float4 zv2 = *(const float4*)(z2 + c);
        float4 zv3 = *(const float4*)(z3 + c);
        float4 wv0 = *(const float4*)(w0 + c);
        float4 wv1 = *(const float4*)(w1 + c);
        float4 wv2 = *(const float4*)(w2 + c);
        float4 wv3 = *(const float4*)(w3 + c);
        float zr[4][4] = {{zv0.x, zv0.y, zv0.z, zv0.w},
                          {zv1.x, zv1.y, zv1.z, zv1.w},
                          {zv2.x, zv2.y, zv2.z, zv2.w},
                          {zv3.x, zv3.y, zv3.z, zv3.w}};
        float wr[4][4] = {{wv0.x, wv0.y, wv0.z, wv0.w},
                          {wv1.x, wv1.y, wv1.z, wv1.w},
                          {wv2.x, wv2.y, wv2.z, wv2.w},
                          {wv3.x, wv3.y, wv3.z, wv3.w}};
        #pragma unroll
        for (int r = 0; r < 4; r++)
            #pragma unroll
            for (int h = 0; h < 4; h++)
                acc[r][h] += zr[r][0] * wr[h][0] + zr[r][1] * wr[h][1]
                           + zr[r][2] * wr[h][2] + zr[r][3] * wr[h][3];
    }

    if (warp >= 4) {
        float* p = part + (hq * 32 + lane) * 17;
        #pragma unroll
        for (int r = 0; r < 4; r++)
            #pragma unroll
            for (int h = 0; h < 4; h++)
                p[r * 4 + h] = acc[r][h];
    }
    __syncthreads();
    if (warp < 4) {
        const float* p = part + (hq * 32 + lane) * 17;
        #pragma unroll
        for (int rr = 0; rr < 4; rr++) {
            int row = lane + rr * 32;
            float m = smean[row], r = srstd[row];
            #pragma unroll
            for (int hh = 0; hh < 4; hh++) {
                int h = hq * 4 + hh;
                float v = acc[rr][hh] + p[rr * 4 + hh];
                g_bias[((size_t)h * NN + i) * NN + j0 + row] =
                    r * (v - m * cs_s[h]) + cc_s[h];
            }
        }
    }
}

// ---------------- K4: attention — vectorized K/V, 2 q-rows per pass ----------------
__global__ void attn_kernel() {
    extern __shared__ float smem[];
    float* ks   = smem;                  // 512 x 28
    float* vs   = ks + 512 * KST;        // 512 x 28
    float* qs   = vs + 512 * KST;        // 32 x 28
    float* wbuf = qs + 32 * KST;         // 8 x 48

    int h  = blockIdx.y;
    int q0 = blockIdx.x * 32;
    int tid = threadIdx.x, lane = tid & 31, warp = tid >> 5;

    for (int idx = tid; idx < 512 * 24; idx += 256) {
        int n = idx / 24, d = idx - n * 24;
        const float* row = g_qkvg + n * (4 * CS);
        ks[n * KST + d] = row[CS + h * HD + d];
        vs[n * KST + d] = row[2 * CS + h * HD + d];
    }
    for (int idx = tid; idx < 32 * 24; idx += 256) {
        int n = idx / 24, d = idx - n * 24;
        qs[n * KST + d] = g_qkvg[(q0 + n) * (4 * CS) + h * HD + d];
    }
    __syncthreads();

    for (int qp2 = 0; qp2 < 2; qp2++) {
        int r0 = warp * 4 + qp2 * 2;     // local q rows r0, r0+1
        int qrow0 = q0 + r0, qrow1 = qrow0 + 1;

        float4 qa[6], qb[6];
        #pragma unroll
        for (int c = 0; c < 6; c++) {
            qa[c] = *(const float4*)(qs + r0 * KST + c * 4);
            qb[c] = *(const float4*)(qs + (r0 + 1) * KST + c * 4);
        }
        const float* brow0 = g_bias + ((size_t)h * NN + qrow0) * NN;
        const float* brow1 = g_bias + ((size_t)h * NN + qrow1) * NN;

        float e0[16], e1[16];
        float mx0 = -1e30f, mx1 = -1e30f;
        #pragma unroll
        for (int jj = 0; jj < 16; jj++) {
            int j = jj * 32 + lane;
            const float* kp = ks + j * KST;
            float s0 = 0.f, s1 = 0.f;
            #pragma unroll
            for (int c = 0; c < 6; c++) {
                float4 kv = *(const float4*)(kp + c * 4);
                s0 += qa[c].x * kv.x + qa[c].y * kv.y + qa[c].z * kv.z + qa[c].w * kv.w;
                s1 += qb[c].x * kv.x + qb[c].y * kv.y + qb[c].z * kv.z + qb[c].w * kv.w;
            }
            s0 += brow0[j];
            s1 += brow1[j];
            e0[jj] = s0; e1[jj] = s1;
            mx0 = fmaxf(mx0, s0); mx1 = fmaxf(mx1, s1);
        }
        #pragma unroll
        for (int o = 16; o > 0; o >>= 1) {
            mx0 = fmaxf(mx0, __shfl_xor_sync(0xFFFFFFFFu, mx0, o));
            mx1 = fmaxf(mx1, __shfl_xor_sync(0xFFFFFFFFu, mx1, o));
        }
        float sum0 = 0.f, sum1 = 0.f;
        #pragma unroll
        for (int jj = 0; jj < 16; jj++) {
            e0[jj] = __expf(e0[jj] - mx0); sum0 += e0[jj];
            e1[jj] = __expf(e1[jj] - mx1); sum1 += e1[jj];
        }
        #pragma unroll
        for (int o = 16; o > 0; o >>= 1) {
            sum0 += __shfl_xor_sync(0xFFFFFFFFu, sum0, o);
            sum1 += __shfl_xor_sync(0xFFFFFFFFu, sum1, o);
        }
        float inv0 = 1.f / sum0, inv1 = 1.f / sum1;

        float4 a0[6], a1[6];
        #pragma unroll
        for (int c = 0; c < 6; c++) {
            a0[c] = make_float4(0.f, 0.f, 0.f, 0.f);
            a1[c] = make_float4(0.f, 0.f, 0.f, 0.f);
        }
        #pragma unroll
        for (int jj = 0; jj < 16; jj++) {
            int j = jj * 32 + lane;
            const float* vp = vs + j * KST;
            float p0 = e0[jj], p1 = e1[jj];
            #pragma unroll
            for (int c = 0; c < 6; c++) {
                float4 vv = *(const float4*)(vp + c * 4);
                a0[c].x += p0 * vv.x; a0[c].y += p0 * vv.y;
                a0[c].z += p0 * vv.z; a0[c].w += p0 * vv.w;
                a1[c].x += p1 * vv.x; a1[c].y += p1 * vv.y;
                a1[c].z += p1 * vv.z; a1[c].w += p1 * vv.w;
            }
        }
        float* wb = wbuf + warp * 48;
        #pragma unroll
        for (int c = 0; c < 6; c++) {
            float v0x = a0[c].x, v0y = a0[c].y, v0z = a0[c].z, v0w = a0[c].w;
            float v1x = a1[c].x, v1y = a1[c].y, v1z = a1[c].z, v1w = a1[c].w;
            #pragma unroll
            for (int o = 16; o > 0; o >>= 1) {
                v0x += __shfl_xor_sync(0xFFFFFFFFu, v0x, o);
                v0y += __shfl_xor_sync(0xFFFFFFFFu, v0y, o);
                v0z += __shfl_xor_sync(0xFFFFFFFFu, v0z, o);
                v0w += __shfl_xor_sync(0xFFFFFFFFu, v0w, o);
                v1x += __shfl_xor_sync(0xFFFFFFFFu, v1x, o);
                v1y += __shfl_xor_sync(0xFFFFFFFFu, v1y, o);
                v1z += __shfl_xor_sync(0xFFFFFFFFu, v1z, o);
                v1w += __shfl_xor_sync(0xFFFFFFFFu, v1w, o);
            }
            if (lane == 0) {
                wb[c * 4 + 0] = v0x; wb[c * 4 + 1] = v0y;
                wb[c * 4 + 2] = v0z; wb[c * 4 + 3] = v0w;
                wb[24 + c * 4 + 0] = v1x; wb[24 + c * 4 + 1] = v1y;
                wb[24 + c * 4 + 2] = v1z; wb[24 + c * 4 + 3] = v1w;
            }
        }
        __syncwarp();
        // writeback: lanes 0..23 handle row0 then row1 (fixed predicate bug)
        if (lane < 24) {
            float ov0 = wb[lane] * inv0;
            float gv0 = g_qkvg[qrow0 * (4 * CS) + 3 * CS + h * HD + lane];
            g_att[qrow0 * CS + h * HD + lane] = ov0 * gv0;
            float ov1 = wb[24 + lane] * inv1;
            float gv1 = g_qkvg[qrow1 * (4 * CS) + 3 * CS + h * HD + lane];
            g_att[qrow1 * CS + h * HD + lane] = ov1 * gv1;
        }
        __syncwarp();
    }
}

// ---------------- K5: output projection ----------------
__global__ void outproj_kernel(const float* __restrict__ Wo, const float* __restrict__ bo,
                               float* __restrict__ out) {
    __shared__ float As[16][64];
    __shared__ float Bs[16][68];
    int bm = blockIdx.y * 64, bn = blockIdx.x * 64;
    int tid = threadIdx.x;
    int tx = tid & 15, ty = tid >> 4;
    int arow = tid >> 2, acol4 = (tid & 3) * 4;
    int brow = tid >> 4, bcol4 = (tid & 15) * 4;
    float acc[4][4] = {};

    for (int k0 = 0; k0 < CS; k0 += 16) {
        float4 av = *(const float4*)(g_att + (bm + arow) * CS + k0 + acol4);
        As[acol4 + 0][arow] = av.x;
        As[acol4 + 1][arow] = av.y;
        As[acol4 + 2][arow] = av.z;
        As[acol4 + 3][arow] = av.w;
        float4 bv = *(const float4*)(Wo + (k0 + brow) * CS + bn + bcol4);
        *(float4*)&Bs[brow][bcol4] = bv;
        __syncthreads();
        #pragma unroll
        for (int kk = 0; kk < 16; kk++) {
            float4 a4 = *(const float4*)&As[kk][ty * 4];
            float4 b4 = *(const float4*)&Bs[kk][tx * 4];
            float af[4] = {a4.x, a4.y, a4.z, a4.w};
            float bf[4] = {b4.x, b4.y, b4.z, b4.w};
            #pragma unroll
            for (int i = 0; i < 4; i++)
                #pragma unroll
                for (int j = 0; j < 4; j++)
                    acc[i][j] += af[i] * bf[j];
        }
        __syncthreads();
    }
    #pragma unroll
    for (int i = 0; i < 4; i++) {
        int row = bm + ty * 4 + i;
        float* o = out + row * CS + bn + tx * 4;
        #pragma unroll
        for (int j = 0; j < 4; j++)
            o[j] = acc[i][j] + bo[bn + tx * 4 + j];
    }
}

// ---------------- launch ----------------
extern "C" void kernel_launch(void* const* d_in, const int* in_sizes, int n_in,
                              void* d_out, int out_size) {
    (void)in_sizes; (void)n_in; (void)out_size;
    const float* a   = (const float*)d_in[0];
    const float* z   = (const float*)d_in[1];
    const float* g_a = (const float*)d_in[2];
    const float* b_a = (const float*)d_in[3];
    const float* g_z = (const float*)d_in[4];
    const float* b_z = (const float*)d_in[5];
    const float* Wz  = (const float*)d_in[6];
    const float* bz  = (const float*)d_in[7];
    const float* Wq  = (const float*)d_in[8];
    const float* Wk  = (const float*)d_in[9];
    const float* Wv  = (const float*)d_in[10];
    const float* Wg  = (const float*)d_in[11];
    const float* bg  = (const float*)d_in[12];
    const float* Wo  = (const float*)d_in[13];
    const float* bo  = (const float*)d_in[14];
    float* out = (float*)d_out;

    cudaFuncSetAttribute(pair_bias_kernel, cudaFuncAttributeMaxDynamicSharedMemorySize, PB_SMEM_BYTES);
    cudaFuncSetAttribute(attn_kernel, cudaFuncAttributeMaxDynamicSharedMemorySize, ATTN_SMEM_BYTES);

    prep_kernel<<<1, 128>>>(g_z, b_z, Wz, bz);
    ln_a_kernel<<<NN, 128>>>(a, g_a, b_a);
    qkvg_kernel<<<dim3(6, 8, 4), 256>>>(Wq, Wk, Wv, Wg, bg);
    pair_bias_kernel<<<dim3(4, NN), 256, PB_SMEM_BYTES>>>(z);
    attn_kernel<<<dim3(16, 16), 256, ATTN_SMEM_BYTES>>>();
    outproj_kernel<<<dim3(6, 8), 256>>>(Wo, bo, out);
}

// round 11
// speedup vs baseline: 1.3267x; 1.1894x over previous
#include <cuda_runtime.h>
#include <math.h>

#define NN 512
#define CS 384
#define CZ 128
#define NH 16
#define HD 24
#define EPS 1e-5f
#define ZST 132   // padded z row stride; 16B-aligned, (ZST/4)%8==1 -> LDS.128 conflict-free
#define KST 28    // padded K/V row stride; 16B-aligned -> LDS.128 conflict-free

// pair_bias smem layout (floats)
#define PB_ZS     (128 * ZST)
#define PB_WS     (NH * CZ)
#define PB_STATS  (256)
#define PB_PART   (4 * 32 * 17)
#define PB_SMEM_FLOATS (PB_ZS + PB_WS + PB_STATS + PB_PART)
#define PB_SMEM_BYTES  (PB_SMEM_FLOATS * 4)   // 85504 (>= qkvg's 8704 -> shared alloc)

// attn smem: ks(512*28) + vs(512*28) + qs(64*28) + wbuf(8*48)
#define ATTN_SMEM_FLOATS (512 * KST * 2 + 64 * KST + 8 * 48)
#define ATTN_SMEM_BYTES  (ATTN_SMEM_FLOATS * 4)   // 123392

// ---------------- scratch ----------------
__device__ float g_an[NN * CS];
__device__ float g_qkvg[NN * 4 * CS];          // [q(pre-scaled) | k | v | g(sigmoid)]
__device__ float g_bias[(size_t)NH * NN * NN]; // [h][i][j]
__device__ float g_att[NN * CS];
__device__ float g_gwT[NH * CZ];
__device__ float g_colsum[NH];
__device__ float g_cconst[NH];

// ---------------- K1: fused prep (block 512) + LN(a) (blocks 0..511) ----------------
__global__ void prep_ln_kernel(const float* __restrict__ a, const float* __restrict__ ga,
                               const float* __restrict__ ba,
                               const float* __restrict__ gz, const float* __restrict__ bzln,
                               const float* __restrict__ Wz, const float* __restrict__ bz) {
    if (blockIdx.x == NN) {
        // prep role
        int c = threadIdx.x;  // 128
        float g = gz[c];
        #pragma unroll
        for (int h = 0; h < NH; h++) g_gwT[h * CZ + c] = g * Wz[c * NH + h];
        __syncthreads();
        if (c < NH) {
            float cs = 0.f, ct = bz[c];
            for (int k = 0; k < CZ; k++) {
                cs += g_gwT[c * CZ + k];
                ct += bzln[k] * Wz[k * NH + c];
            }
            g_colsum[c] = cs;
            g_cconst[c] = ct;
        }
        return;
    }
    int row = blockIdx.x, t = threadIdx.x;  // 128 threads
    const float* x = a + row * CS;
    float v0 = x[t], v1 = x[t + 128], v2 = x[t + 256];
    float s = v0 + v1 + v2;
    float q = v0 * v0 + v1 * v1 + v2 * v2;
    __shared__ float rs[4], rq[4];
    #pragma unroll
    for (int o = 16; o > 0; o >>= 1) {
        s += __shfl_xor_sync(0xFFFFFFFFu, s, o);
        q += __shfl_xor_sync(0xFFFFFFFFu, q, o);
    }
    if ((t & 31) == 0) { rs[t >> 5] = s; rq[t >> 5] = q; }
    __syncthreads();
    float S = rs[0] + rs[1] + rs[2] + rs[3];
    float Q = rq[0] + rq[1] + rq[2] + rq[3];
    float m = S * (1.f / CS);
    float var = Q * (1.f / CS) - m * m;
    float r = rsqrtf(var + EPS);
    float* o = g_an + row * CS;
    o[t]       = (v0 - m) * r * ga[t]       + ba[t];
    o[t + 128] = (v1 - m) * r * ga[t + 128] + ba[t + 128];
    o[t + 256] = (v2 - m) * r * ga[t + 256] + ba[t + 256];
}

// ---------------- qkvg role body ----------------
__device__ __forceinline__ void qkvg_body(float* smem, int mat, int bm, int bn,
                                          const float* __restrict__ Wq, const float* __restrict__ Wk,
                                          const float* __restrict__ Wv, const float* __restrict__ Wg,
                                          const float* __restrict__ bg) {
    float* As = smem;              // [16][64]
    float* Bs = smem + 16 * 64;    // [16][68]
    const float* B = (mat == 0) ? Wq : (mat == 1) ? Wk : (mat == 2) ? Wv : Wg;
    int tid = threadIdx.x;         // 256
    int tx = tid & 15, ty = tid >> 4;
    int arow = tid >> 2, acol4 = (tid & 3) * 4;
    int brow = tid >> 4, bcol4 = (tid & 15) * 4;
    float acc[4][4] = {};

    for (int k0 = 0; k0 < CS; k0 += 16) {
        float4 av = *(const float4*)(g_an + (bm + arow) * CS + k0 + acol4);
        As[(acol4 + 0) * 64 + arow] = av.x;
        As[(acol4 + 1) * 64 + arow] = av.y;
        As[(acol4 + 2) * 64 + arow] = av.z;
        As[(acol4 + 3) * 64 + arow] = av.w;
        float4 bv = *(const float4*)(B + (k0 + brow) * CS + bn + bcol4);
        *(float4*)&Bs[brow * 68 + bcol4] = bv;
        __syncthreads();
        #pragma unroll
        for (int kk = 0; kk < 16; kk++) {
            float4 a4 = *(const float4*)&As[kk * 64 + ty * 4];
            float4 b4 = *(const float4*)&Bs[kk * 68 + tx * 4];
            float af[4] = {a4.x, a4.y, a4.z, a4.w};
            float bf[4] = {b4.x, b4.y, b4.z, b4.w};
            #pragma unroll
            for (int i = 0; i < 4; i++)
                #pragma unroll
                for (int j = 0; j < 4; j++)
                    acc[i][j] += af[i] * bf[j];
        }
        __syncthreads();
    }
    int colbase = mat * CS + bn + tx * 4;
    #pragma unroll
    for (int i = 0; i < 4; i++) {
        int row = bm + ty * 4 + i;
        float* out = g_qkvg + row * (4 * CS) + colbase;
        #pragma unroll
        for (int j = 0; j < 4; j++) {
            float v = acc[i][j];
            if (mat == 0) v *= 0.2041241452319315f;  // 1/sqrt(24)
            else if (mat == 3) v = 1.f / (1.f + __expf(-(v + bg[bn + tx * 4 + j])));
            out[j] = v;
        }
    }
}

// ---------------- pair_bias role body ----------------
__device__ __forceinline__ void pair_bias_body(float* smem, const float* __restrict__ z,
                                               int i, int j0) {
    float* zs    = smem;                 // 128 x ZST
    float* ws    = zs + PB_ZS;           // 16 x 128
    float* smean = ws + PB_WS;           // 128
    float* srstd = smean + 128;          // 128
    float* part  = srstd + 128;          // [4 hq][32 lane][17]
    __shared__ float cs_s[NH], cc_s[NH];

    int t = threadIdx.x;                 // 256
    int lane = t & 31, warp = t >> 5;    // 8 warps

    #pragma unroll
    for (int k = 0; k < PB_WS / 256; k++) ws[t + 256 * k] = g_gwT[t + 256 * k];
    if (t < NH) { cs_s[t] = g_colsum[t]; cc_s[t] = g_cconst[t]; }

    const float4* src = (const float4*)(z + ((size_t)i * NN + j0) * CZ);
    #pragma unroll
    for (int k = 0; k < 16; k++) {
        int idx = t + 256 * k;
        int row = idx >> 5, c4 = idx & 31;
        *(float4*)(zs + row * ZST + c4 * 4) = src[idx];
    }
    __syncthreads();

    {
        int row = t >> 1, half = t & 1;
        const float* zr = zs + row * ZST + half * 64;
        float s0 = 0, s1 = 0, s2 = 0, s3 = 0;
        float q0 = 0, q1 = 0, q2 = 0, q3 = 0;
        #pragma unroll
        for (int c = 0; c < 64; c += 4) {
            float4 v = *(const float4*)(zr + c);
            s0 += v.x; s1 += v.y; s2 += v.z; s3 += v.w;
            q0 += v.x * v.x; q1 += v.y * v.y; q2 += v.z * v.z; q3 += v.w * v.w;
        }
        float s = (s0 + s1) + (s2 + s3);
        float q = (q0 + q1) + (q2 + q3);
        s += __shfl_xor_sync(0xFFFFFFFFu, s, 1);
        q += __shfl_xor_sync(0xFFFFFFFFu, q, 1);
        if (half == 0) {
            float m = s * (1.f / 128.f);
            float var = q * (1.f / 128.f) - m * m;
            smean[row] = m;
            srstd[row] = rsqrtf(var + EPS);
        }
    }
    __syncthreads();

    int hq = warp & 3;
    int cbase = (warp >> 2) * 64;
    const float* z0 = zs + (lane +  0) * ZST + cbase;
    const float* z1 = zs + (lane + 32) * ZST + cbase;
    const float* z2 = zs + (lane + 64) * ZST + cbase;
    const float* z3 = zs + (lane + 96) * ZST + cbase;
    const float* w0 = ws + (hq * 4 + 0) * CZ + cbase;
    const float* w1 = ws + (hq * 4 + 1) * CZ + cbase;
    const float* w2 = ws + (hq * 4 + 2) * CZ + cbase;
    const float* w3 = ws + (hq * 4 + 3) * CZ + cbase;
    float acc[4][4] = {};
    #pragma unroll 4
    for (int c = 0; c < 64; c += 4) {
        float4 zv0 = *(const float4*)(z0 + c);
        float4 zv1 = *(const float4*)(z1 + c);
        float4 zv2 = *(const float4*)(z2 + c);
        float4 zv3 = *(const float4*)(z3 + c);
        float4 wv0 = *(const float4*)(w0 + c);
        float4 wv1 = *(const float4*)(w1 + c);
        float4 wv2 = *(const float4*)(w2 + c);
        float4 wv3 = *(const float4*)(w3 + c);
        float zr[4][4] = {{zv0.x, zv0.y, zv0.z, zv0.w},
                          {zv1.x, zv1.y, zv1.z, zv1.w},
                          {zv2.x, zv2.y, zv2.z, zv2.w},
                          {zv3.x, zv3.y, zv3.z, zv3.w}};
        float wr[4][4] = {{wv0.x, wv0.y, wv0.z, wv0.w},
                          {wv1.x, wv1.y, wv1.z, wv1.w},
                          {wv2.x, wv2.y, wv2.z, wv2.w},
                          {wv3.x, wv3.y, wv3.z, wv3.w}};
        #pragma unroll
        for (int r = 0; r < 4; r++)
            #pragma unroll
            for (int h = 0; h < 4; h++)
                acc[r][h] += zr[r][0] * wr[h][0] + zr[r][1] * wr[h][1]
                           + zr[r][2] * wr[h][2] + zr[r][3] * wr[h][3];
    }

    if (warp >= 4) {
        float* p = part + (hq * 32 + lane) * 17;
        #pragma unroll
        for (int r = 0; r < 4; r++)
            #pragma unroll
            for (int h = 0; h < 4; h++)
                p[r * 4 + h] = acc[r][h];
    }
    __syncthreads();
    if (warp < 4) {
        const float* p = part + (hq * 32 + lane) * 17;
        #pragma unroll
        for (int rr = 0; rr < 4; rr++) {
            int row = lane + rr * 32;
            float m = smean[row], r = srstd[row];
            #pragma unroll
            for (int hh = 0; hh < 4; hh++) {
                int h = hq * 4 + hh;
                float v = acc[rr][hh] + p[rr * 4 + hh];
                g_bias[((size_t)h * NN + i) * NN + j0 + row] =
                    r * (v - m * cs_s[h]) + cc_s[h];
            }
        }
    }
}

// ---------------- K2: merged pair_bias + qkvg (independent work, co-resident) ----------------
// blocks 0..191: qkvg roles (scheduled first); blocks 192..2239: pair_bias tiles.
__global__ void __launch_bounds__(256) fused_mid_kernel(
    const float* __restrict__ z,
    const float* __restrict__ Wq, const float* __restrict__ Wk,
    const float* __restrict__ Wv, const float* __restrict__ Wg,
    const float* __restrict__ bg) {
    extern __shared__ float smem[];
    if (blockIdx.x < 192) {
        int b = blockIdx.x;
        int mat = b >> 6;            // 0..2 for first 192? no: 192/48=4 mats of 48
        mat = b / 48;
        int rem = b - mat * 48;
        int bx = rem % 6, by = rem / 6;
        qkvg_body(smem, mat, by * 64, bx * 64, Wq, Wk, Wv, Wg, bg);
    } else {
        int pb = blockIdx.x - 192;   // 0..2047
        int i = pb >> 2;
        int j0 = (pb & 3) * 128;
        pair_bias_body(smem, z, i, j0);
    }
}

// ---------------- K3: attention — 64-row q-tiles, grid (8,16)=128 blocks (1 wave) ----------------
__global__ void attn_kernel() {
    extern __shared__ float smem[];
    float* ks   = smem;                  // 512 x 28
    float* vs   = ks + 512 * KST;        // 512 x 28
    float* qs   = vs + 512 * KST;        // 64 x 28
    float* wbuf = qs + 64 * KST;         // 8 x 48

    int h  = blockIdx.y;
    int q0 = blockIdx.x * 64;
    int tid = threadIdx.x, lane = tid & 31, warp = tid >> 5;

    for (int idx = tid; idx < 512 * 24; idx += 256) {
        int n = idx / 24, d = idx - n * 24;
        const float* row = g_qkvg + n * (4 * CS);
        ks[n * KST + d] = row[CS + h * HD + d];
        vs[n * KST + d] = row[2 * CS + h * HD + d];
    }
    for (int idx = tid; idx < 64 * 24; idx += 256) {
        int n = idx / 24, d = idx - n * 24;
        qs[n * KST + d] = g_qkvg[(q0 + n) * (4 * CS) + h * HD + d];
    }
    __syncthreads();

    for (int qp2 = 0; qp2 < 4; qp2++) {
        int r0 = warp * 8 + qp2 * 2;     // local q rows r0, r0+1
        int qrow0 = q0 + r0, qrow1 = qrow0 + 1;

        float4 qa[6], qb[6];
        #pragma unroll
        for (int c = 0; c < 6; c++) {
            qa[c] = *(const float4*)(qs + r0 * KST + c * 4);
            qb[c] = *(const float4*)(qs + (r0 + 1) * KST + c * 4);
        }
        const float* brow0 = g_bias + ((size_t)h * NN + qrow0) * NN;
        const float* brow1 = g_bias + ((size_t)h * NN + qrow1) * NN;

        float e0[16], e1[16];
        float mx0 = -1e30f, mx1 = -1e30f;
        #pragma unroll
        for (int jj = 0; jj < 16; jj++) {
            int j = jj * 32 + lane;
            const float* kp = ks + j * KST;
            float s0 = 0.f, s1 = 0.f;
            #pragma unroll
            for (int c = 0; c < 6; c++) {
                float4 kv = *(const float4*)(kp + c * 4);
                s0 += qa[c].x * kv.x + qa[c].y * kv.y + qa[c].z * kv.z + qa[c].w * kv.w;
                s1 += qb[c].x * kv.x + qb[c].y * kv.y + qb[c].z * kv.z + qb[c].w * kv.w;
            }
            s0 += brow0[j];
            s1 += brow1[j];
            e0[jj] = s0; e1[jj] = s1;
            mx0 = fmaxf(mx0, s0); mx1 = fmaxf(mx1, s1);
        }
        #pragma unroll
        for (int o = 16; o > 0; o >>= 1) {
            mx0 = fmaxf(mx0, __shfl_xor_sync(0xFFFFFFFFu, mx0, o));
            mx1 = fmaxf(mx1, __shfl_xor_sync(0xFFFFFFFFu, mx1, o));
        }
        float sum0 = 0.f, sum1 = 0.f;
        #pragma unroll
        for (int jj = 0; jj < 16; jj++) {
            e0[jj] = __expf(e0[jj] - mx0); sum0 += e0[jj];
            e1[jj] = __expf(e1[jj] - mx1); sum1 += e1[jj];
        }
        #pragma unroll
        for (int o = 16; o > 0; o >>= 1) {
            sum0 += __shfl_xor_sync(0xFFFFFFFFu, sum0, o);
            sum1 += __shfl_xor_sync(0xFFFFFFFFu, sum1, o);
        }
        float inv0 = 1.f / sum0, inv1 = 1.f / sum1;

        float4 a0[6], a1[6];
        #pragma unroll
        for (int c = 0; c < 6; c++) {
            a0[c] = make_float4(0.f, 0.f, 0.f, 0.f);
            a1[c] = make_float4(0.f, 0.f, 0.f, 0.f);
        }
        #pragma unroll
        for (int jj = 0; jj < 16; jj++) {
            int j = jj * 32 + lane;
            const float* vp = vs + j * KST;
            float p0 = e0[jj], p1 = e1[jj];
            #pragma unroll
            for (int c = 0; c < 6; c++) {
                float4 vv = *(const float4*)(vp + c * 4);
                a0[c].x += p0 * vv.x; a0[c].y += p0 * vv.y;
                a0[c].z += p0 * vv.z; a0[c].w += p0 * vv.w;
                a1[c].x += p1 * vv.x; a1[c].y += p1 * vv.y;
                a1[c].z += p1 * vv.z; a1[c].w += p1 * vv.w;
            }
        }
        float* wb = wbuf + warp * 48;
        #pragma unroll
        for (int c = 0; c < 6; c++) {
            float v0x = a0[c].x, v0y = a0[c].y, v0z = a0[c].z, v0w = a0[c].w;
            float v1x = a1[c].x, v1y = a1[c].y, v1z = a1[c].z, v1w = a1[c].w;
            #pragma unroll
            for (int o = 16; o > 0; o >>= 1) {
                v0x += __shfl_xor_sync(0xFFFFFFFFu, v0x, o);
                v0y += __shfl_xor_sync(0xFFFFFFFFu, v0y, o);
                v0z += __shfl_xor_sync(0xFFFFFFFFu, v0z, o);
                v0w += __shfl_xor_sync(0xFFFFFFFFu, v0w, o);
                v1x += __shfl_xor_sync(0xFFFFFFFFu, v1x, o);
                v1y += __shfl_xor_sync(0xFFFFFFFFu, v1y, o);
                v1z += __shfl_xor_sync(0xFFFFFFFFu, v1z, o);
                v1w += __shfl_xor_sync(0xFFFFFFFFu, v1w, o);
            }
            if (lane == 0) {
                wb[c * 4 + 0] = v0x; wb[c * 4 + 1] = v0y;
                wb[c * 4 + 2] = v0z; wb[c * 4 + 3] = v0w;
                wb[24 + c * 4 + 0] = v1x; wb[24 + c * 4 + 1] = v1y;
                wb[24 + c * 4 + 2] = v1z; wb[24 + c * 4 + 3] = v1w;
            }
        }
        __syncwarp();
        if (lane < 24) {
            float ov0 = wb[lane] * inv0;
            float gv0 = g_qkvg[qrow0 * (4 * CS) + 3 * CS + h * HD + lane];
            g_att[qrow0 * CS + h * HD + lane] = ov0 * gv0;
            float ov1 = wb[24 + lane] * inv1;
            float gv1 = g_qkvg[qrow1 * (4 * CS) + 3 * CS + h * HD + lane];
            g_att[qrow1 * CS + h * HD + lane] = ov1 * gv1;
        }
        __syncwarp();
    }
}

// ---------------- K4: output projection ----------------
__global__ void outproj_kernel(const float* __restrict__ Wo, const float* __restrict__ bo,
                               float* __restrict__ out) {
    __shared__ float As[16][64];
    __shared__ float Bs[16][68];
    int bm = blockIdx.y * 64, bn = blockIdx.x * 64;
    int tid = threadIdx.x;
    int tx = tid & 15, ty = tid >> 4;
    int arow = tid >> 2, acol4 = (tid & 3) * 4;
    int brow = tid >> 4, bcol4 = (tid & 15) * 4;
    float acc[4][4] = {};

    for (int k0 = 0; k0 < CS; k0 += 16) {
        float4 av = *(const float4*)(g_att + (bm + arow) * CS + k0 + acol4);
        As[acol4 + 0][arow] = av.x;
        As[acol4 + 1][arow] = av.y;
        As[acol4 + 2][arow] = av.z;
        As[acol4 + 3][arow] = av.w;
        float4 bv = *(const float4*)(Wo + (k0 + brow) * CS + bn + bcol4);
        *(float4*)&Bs[brow][bcol4] = bv;
        __syncthreads();
        #pragma unroll
        for (int kk = 0; kk < 16; kk++) {
            float4 a4 = *(const float4*)&As[kk][ty * 4];
            float4 b4 = *(const float4*)&Bs[kk][tx * 4];
            float af[4] = {a4.x, a4.y, a4.z, a4.w};
            float bf[4] = {b4.x, b4.y, b4.z, b4.w};
            #pragma unroll
            for (int i = 0; i < 4; i++)
                #pragma unroll
                for (int j = 0; j < 4; j++)
                    acc[i][j] += af[i] * bf[j];
        }
        __syncthreads();
    }
    #pragma unroll
    for (int i = 0; i < 4; i++) {
        int row = bm + ty * 4 + i;
        float* o = out + row * CS + bn + tx * 4;
        #pragma unroll
        for (int j = 0; j < 4; j++)
            o[j] = acc[i][j] + bo[bn + tx * 4 + j];
    }
}

// ---------------- launch ----------------
extern "C" void kernel_launch(void* const* d_in, const int* in_sizes, int n_in,
                              void* d_out, int out_size) {
    (void)in_sizes; (void)n_in; (void)out_size;
    const float* a   = (const float*)d_in[0];
    const float* z   = (const float*)d_in[1];
    const float* g_a = (const float*)d_in[2];
    const float* b_a = (const float*)d_in[3];
    const float* g_z = (const float*)d_in[4];
    const float* b_z = (const float*)d_in[5];
    const float* Wz  = (const float*)d_in[6];
    const float* bz  = (const float*)d_in[7];
    const float* Wq  = (const float*)d_in[8];
    const float* Wk  = (const float*)d_in[9];
    const float* Wv  = (const float*)d_in[10];
    const float* Wg  = (const float*)d_in[11];
    const float* bg  = (const float*)d_in[12];
    const float* Wo  = (const float*)d_in[13];
    const float* bo  = (const float*)d_in[14];
    float* out = (float*)d_out;

    cudaFuncSetAttribute(fused_mid_kernel, cudaFuncAttributeMaxDynamicSharedMemorySize, PB_SMEM_BYTES);
    cudaFuncSetAttribute(attn_kernel, cudaFuncAttributeMaxDynamicSharedMemorySize, ATTN_SMEM_BYTES);

    prep_ln_kernel<<<NN + 1, 128>>>(a, g_a, b_a, g_z, b_z, Wz, bz);
    fused_mid_kernel<<<192 + 2048, 256, PB_SMEM_BYTES>>>(z, Wq, Wk, Wv, Wg, bg);
    attn_kernel<<<dim3(8, 16), 256, ATTN_SMEM_BYTES>>>();
    outproj_kernel<<<dim3(6, 8), 256>>>(Wo, bo, out);
}

// round 12
// speedup vs baseline: 1.4873x; 1.1211x over previous
#include <cuda_runtime.h>
#include <math.h>

#define NN 512
#define CS 384
#define CZ 128
#define NH 16
#define HD 24
#define EPS 1e-5f
#define ZST 132   // padded z row stride; 16B-aligned, (ZST/4)%8==1 -> LDS.128 conflict-free
#define KST 28    // padded K/V row stride; 16B-aligned -> LDS.128 conflict-free

// pair_bias smem layout (floats)
#define PB_ZS     (128 * ZST)
#define PB_WS     (NH * CZ)
#define PB_STATS  (256)
#define PB_PART   (4 * 32 * 17)
#define PB_SMEM_FLOATS (PB_ZS + PB_WS + PB_STATS + PB_PART)
#define PB_SMEM_BYTES  (PB_SMEM_FLOATS * 4)   // 85504

// attn smem: ks(512*28) + vs(512*28) + qs(64*28) + wbuf(8*48)
#define ATTN_SMEM_FLOATS (512 * KST * 2 + 64 * KST + 8 * 48)
#define ATTN_SMEM_BYTES  (ATTN_SMEM_FLOATS * 4)   // 123392

// ---------------- scratch ----------------
__device__ float g_an[NN * CS];
__device__ float g_qkvg[NN * 4 * CS];          // [q(pre-scaled) | k | v | g(sigmoid)]
__device__ float g_bias[(size_t)NH * NN * NN]; // [h][i][j]
__device__ float g_att[NN * CS];
__device__ float g_gwT[NH * CZ];
__device__ float g_colsum[NH];
__device__ float g_cconst[NH];

// ---------------- K1: fused prep (block 512) + LN(a) + out=bias init ----------------
__global__ void prep_ln_kernel(const float* __restrict__ a, const float* __restrict__ ga,
                               const float* __restrict__ ba,
                               const float* __restrict__ gz, const float* __restrict__ bzln,
                               const float* __restrict__ Wz, const float* __restrict__ bz,
                               const float* __restrict__ bo, float* __restrict__ out) {
    if (blockIdx.x == NN) {
        // prep role
        int c = threadIdx.x;  // 128
        float g = gz[c];
        #pragma unroll
        for (int h = 0; h < NH; h++) g_gwT[h * CZ + c] = g * Wz[c * NH + h];
        __syncthreads();
        if (c < NH) {
            float cs = 0.f, ct = bz[c];
            for (int k = 0; k < CZ; k++) {
                cs += g_gwT[c * CZ + k];
                ct += bzln[k] * Wz[k * NH + c];
            }
            g_colsum[c] = cs;
            g_cconst[c] = ct;
        }
        return;
    }
    int row = blockIdx.x, t = threadIdx.x;  // 128 threads
    const float* x = a + row * CS;
    float v0 = x[t], v1 = x[t + 128], v2 = x[t + 256];
    float s = v0 + v1 + v2;
    float q = v0 * v0 + v1 * v1 + v2 * v2;
    __shared__ float rs[4], rq[4];
    #pragma unroll
    for (int o = 16; o > 0; o >>= 1) {
        s += __shfl_xor_sync(0xFFFFFFFFu, s, o);
        q += __shfl_xor_sync(0xFFFFFFFFu, q, o);
    }
    if ((t & 31) == 0) { rs[t >> 5] = s; rq[t >> 5] = q; }
    __syncthreads();
    float S = rs[0] + rs[1] + rs[2] + rs[3];
    float Q = rq[0] + rq[1] + rq[2] + rq[3];
    float m = S * (1.f / CS);
    float var = Q * (1.f / CS) - m * m;
    float r = rsqrtf(var + EPS);
    float* o = g_an + row * CS;
    o[t]       = (v0 - m) * r * ga[t]       + ba[t];
    o[t + 128] = (v1 - m) * r * ga[t + 128] + ba[t + 128];
    o[t + 256] = (v2 - m) * r * ga[t + 256] + ba[t + 256];
    // init out rows with bias (consumed by atomicAdd k-split outproj)
    float* orow = out + row * CS;
    orow[t]       = bo[t];
    orow[t + 128] = bo[t + 128];
    orow[t + 256] = bo[t + 256];
}

// ---------------- qkvg role body ----------------
__device__ __forceinline__ void qkvg_body(float* smem, int mat, int bm, int bn,
                                          const float* __restrict__ Wq, const float* __restrict__ Wk,
                                          const float* __restrict__ Wv, const float* __restrict__ Wg,
                                          const float* __restrict__ bg) {
    float* As = smem;              // [16][64]
    float* Bs = smem + 16 * 64;    // [16][68]
    const float* B = (mat == 0) ? Wq : (mat == 1) ? Wk : (mat == 2) ? Wv : Wg;
    int tid = threadIdx.x;         // 256
    int tx = tid & 15, ty = tid >> 4;
    int arow = tid >> 2, acol4 = (tid & 3) * 4;
    int brow = tid >> 4, bcol4 = (tid & 15) * 4;
    float acc[4][4] = {};

    for (int k0 = 0; k0 < CS; k0 += 16) {
        float4 av = *(const float4*)(g_an + (bm + arow) * CS + k0 + acol4);
        As[(acol4 + 0) * 64 + arow] = av.x;
        As[(acol4 + 1) * 64 + arow] = av.y;
        As[(acol4 + 2) * 64 + arow] = av.z;
        As[(acol4 + 3) * 64 + arow] = av.w;
        float4 bv = *(const float4*)(B + (k0 + brow) * CS + bn + bcol4);
        *(float4*)&Bs[brow * 68 + bcol4] = bv;
        __syncthreads();
        #pragma unroll
        for (int kk = 0; kk < 16; kk++) {
            float4 a4 = *(const float4*)&As[kk * 64 + ty * 4];
            float4 b4 = *(const float4*)&Bs[kk * 68 + tx * 4];
            float af[4] = {a4.x, a4.y, a4.z, a4.w};
            float bf[4] = {b4.x, b4.y, b4.z, b4.w};
            #pragma unroll
            for (int i = 0; i < 4; i++)
                #pragma unroll
                for (int j = 0; j < 4; j++)
                    acc[i][j] += af[i] * bf[j];
        }
        __syncthreads();
    }
    int colbase = mat * CS + bn + tx * 4;
    #pragma unroll
    for (int i = 0; i < 4; i++) {
        int row = bm + ty * 4 + i;
        float* out = g_qkvg + row * (4 * CS) + colbase;
        #pragma unroll
        for (int j = 0; j < 4; j++) {
            float v = acc[i][j];
            if (mat == 0) v *= 0.2041241452319315f;  // 1/sqrt(24)
            else if (mat == 3) v = 1.f / (1.f + __expf(-(v + bg[bn + tx * 4 + j])));
            out[j] = v;
        }
    }
}

// ---------------- pair_bias role body ----------------
__device__ __forceinline__ void pair_bias_body(float* smem, const float* __restrict__ z,
                                               int i, int j0) {
    float* zs    = smem;                 // 128 x ZST
    float* ws    = zs + PB_ZS;           // 16 x 128
    float* smean = ws + PB_WS;           // 128
    float* srstd = smean + 128;          // 128
    float* part  = srstd + 128;          // [4 hq][32 lane][17]
    __shared__ float cs_s[NH], cc_s[NH];

    int t = threadIdx.x;                 // 256
    int lane = t & 31, warp = t >> 5;    // 8 warps

    #pragma unroll
    for (int k = 0; k < PB_WS / 256; k++) ws[t + 256 * k] = g_gwT[t + 256 * k];
    if (t < NH) { cs_s[t] = g_colsum[t]; cc_s[t] = g_cconst[t]; }

    const float4* src = (const float4*)(z + ((size_t)i * NN + j0) * CZ);
    #pragma unroll
    for (int k = 0; k < 16; k++) {
        int idx = t + 256 * k;
        int row = idx >> 5, c4 = idx & 31;
        *(float4*)(zs + row * ZST + c4 * 4) = src[idx];
    }
    __syncthreads();

    {
        int row = t >> 1, half = t & 1;
        const float* zr = zs + row * ZST + half * 64;
        float s0 = 0, s1 = 0, s2 = 0, s3 = 0;
        float q0 = 0, q1 = 0, q2 = 0, q3 = 0;
        #pragma unroll
        for (int c = 0; c < 64; c += 4) {
            float4 v = *(const float4*)(zr + c);
            s0 += v.x; s1 += v.y; s2 += v.z; s3 += v.w;
            q0 += v.x * v.x; q1 += v.y * v.y; q2 += v.z * v.z; q3 += v.w * v.w;
        }
        float s = (s0 + s1) + (s2 + s3);
        float q = (q0 + q1) + (q2 + q3);
        s += __shfl_xor_sync(0xFFFFFFFFu, s, 1);
        q += __shfl_xor_sync(0xFFFFFFFFu, q, 1);
        if (half == 0) {
            float m = s * (1.f / 128.f);
            float var = q * (1.f / 128.f) - m * m;
            smean[row] = m;
            srstd[row] = rsqrtf(var + EPS);
        }
    }
    __syncthreads();

    int hq = warp & 3;
    int cbase = (warp >> 2) * 64;
    const float* z0 = zs + (lane +  0) * ZST + cbase;
    const float* z1 = zs + (lane + 32) * ZST + cbase;
    const float* z2 = zs + (lane + 64) * ZST + cbase;
    const float* z3 = zs + (lane + 96) * ZST + cbase;
    const float* w0 = ws + (hq * 4 + 0) * CZ + cbase;
    const float* w1 = ws + (hq * 4 + 1) * CZ + cbase;
    const float* w2 = ws + (hq * 4 + 2) * CZ + cbase;
    const float* w3 = ws + (hq * 4 + 3) * CZ + cbase;
    float acc[4][4] = {};
    #pragma unroll 4
    for (int c = 0; c < 64; c += 4) {
        float4 zv0 = *(const float4*)(z0 + c);
        float4 zv1 = *(const float4*)(z1 + c);
        float4 zv2 = *(const float4*)(z2 + c);
        float4 zv3 = *(const float4*)(z3 + c);
        float4 wv0 = *(const float4*)(w0 + c);
        float4 wv1 = *(const float4*)(w1 + c);
        float4 wv2 = *(const float4*)(w2 + c);
        float4 wv3 = *(const float4*)(w3 + c);
        float zr[4][4] = {{zv0.x, zv0.y, zv0.z, zv0.w},
                          {zv1.x, zv1.y, zv1.z, zv1.w},
                          {zv2.x, zv2.y, zv2.z, zv2.w},
                          {zv3.x, zv3.y, zv3.z, zv3.w}};
        float wr[4][4] = {{wv0.x, wv0.y, wv0.z, wv0.w},
                          {wv1.x, wv1.y, wv1.z, wv1.w},
                          {wv2.x, wv2.y, wv2.z, wv2.w},
                          {wv3.x, wv3.y, wv3.z, wv3.w}};
        #pragma unroll
        for (int r = 0; r < 4; r++)
            #pragma unroll
            for (int h = 0; h < 4; h++)
                acc[r][h] += zr[r][0] * wr[h][0] + zr[r][1] * wr[h][1]
                           + zr[r][2] * wr[h][2] + zr[r][3] * wr[h][3];
    }

    if (warp >= 4) {
        float* p = part + (hq * 32 + lane) * 17;
        #pragma unroll
        for (int r = 0; r < 4; r++)
            #pragma unroll
            for (int h = 0; h < 4; h++)
                p[r * 4 + h] = acc[r][h];
    }
    __syncthreads();
    if (warp < 4) {
        const float* p = part + (hq * 32 + lane) * 17;
        #pragma unroll
        for (int rr = 0; rr < 4; rr++) {
            int row = lane + rr * 32;
            float m = smean[row], r = srstd[row];
            #pragma unroll
            for (int hh = 0; hh < 4; hh++) {
                int h = hq * 4 + hh;
                float v = acc[rr][hh] + p[rr * 4 + hh];
                g_bias[((size_t)h * NN + i) * NN + j0 + row] =
                    r * (v - m * cs_s[h]) + cc_s[h];
            }
        }
    }
}

// ---------------- K2: merged pair_bias + qkvg ----------------
__global__ void __launch_bounds__(256) fused_mid_kernel(
    const float* __restrict__ z,
    const float* __restrict__ Wq, const float* __restrict__ Wk,
    const float* __restrict__ Wv, const float* __restrict__ Wg,
    const float* __restrict__ bg) {
    extern __shared__ float smem[];
    if (blockIdx.x < 192) {
        int b = blockIdx.x;
        int mat = b / 48;
        int rem = b - mat * 48;
        int bx = rem % 6, by = rem / 6;
        qkvg_body(smem, mat, by * 64, bx * 64, Wq, Wk, Wv, Wg, bg);
    } else {
        int pb = blockIdx.x - 192;   // 0..2047
        int i = pb >> 2;
        int j0 = (pb & 3) * 128;
        pair_bias_body(smem, z, i, j0);
    }
}

// ---------------- K3: attention — 64-row q-tiles, grid (8,16)=128 blocks ----------------
__global__ void attn_kernel() {
    extern __shared__ float smem[];
    float* ks   = smem;                  // 512 x 28
    float* vs   = ks + 512 * KST;        // 512 x 28
    float* qs   = vs + 512 * KST;        // 64 x 28
    float* wbuf = qs + 64 * KST;         // 8 x 48

    int h  = blockIdx.y;
    int q0 = blockIdx.x * 64;
    int tid = threadIdx.x, lane = tid & 31, warp = tid >> 5;

    for (int idx = tid; idx < 512 * 24; idx += 256) {
        int n = idx / 24, d = idx - n * 24;
        const float* row = g_qkvg + n * (4 * CS);
        ks[n * KST + d] = row[CS + h * HD + d];
        vs[n * KST + d] = row[2 * CS + h * HD + d];
    }
    for (int idx = tid; idx < 64 * 24; idx += 256) {
        int n = idx / 24, d = idx - n * 24;
        qs[n * KST + d] = g_qkvg[(q0 + n) * (4 * CS) + h * HD + d];
    }
    __syncthreads();

    for (int qp2 = 0; qp2 < 4; qp2++) {
        int r0 = warp * 8 + qp2 * 2;
        int qrow0 = q0 + r0, qrow1 = qrow0 + 1;

        float4 qa[6], qb[6];
        #pragma unroll
        for (int c = 0; c < 6; c++) {
            qa[c] = *(const float4*)(qs + r0 * KST + c * 4);
            qb[c] = *(const float4*)(qs + (r0 + 1) * KST + c * 4);
        }
        const float* brow0 = g_bias + ((size_t)h * NN + qrow0) * NN;
        const float* brow1 = g_bias + ((size_t)h * NN + qrow1) * NN;

        float e0[16], e1[16];
        float mx0 = -1e30f, mx1 = -1e30f;
        #pragma unroll
        for (int jj = 0; jj < 16; jj++) {
            int j = jj * 32 + lane;
            const float* kp = ks + j * KST;
            float s0 = 0.f, s1 = 0.f;
            #pragma unroll
            for (int c = 0; c < 6; c++) {
                float4 kv = *(const float4*)(kp + c * 4);
                s0 += qa[c].x * kv.x + qa[c].y * kv.y + qa[c].z * kv.z + qa[c].w * kv.w;
                s1 += qb[c].x * kv.x + qb[c].y * kv.y + qb[c].z * kv.z + qb[c].w * kv.w;
            }
            s0 += brow0[j];
            s1 += brow1[j];
            e0[jj] = s0; e1[jj] = s1;
            mx0 = fmaxf(mx0, s0); mx1 = fmaxf(mx1, s1);
        }
        #pragma unroll
        for (int o = 16; o > 0; o >>= 1) {
            mx0 = fmaxf(mx0, __shfl_xor_sync(0xFFFFFFFFu, mx0, o));
            mx1 = fmaxf(mx1, __shfl_xor_sync(0xFFFFFFFFu, mx1, o));
        }
        float sum0 = 0.f, sum1 = 0.f;
        #pragma unroll
        for (int jj = 0; jj < 16; jj++) {
            e0[jj] = __expf(e0[jj] - mx0); sum0 += e0[jj];
            e1[jj] = __expf(e1[jj] - mx1); sum1 += e1[jj];
        }
        #pragma unroll
        for (int o = 16; o > 0; o >>= 1) {
            sum0 += __shfl_xor_sync(0xFFFFFFFFu, sum0, o);
            sum1 += __shfl_xor_sync(0xFFFFFFFFu, sum1, o);
        }
        float inv0 = 1.f / sum0, inv1 = 1.f / sum1;

        float4 a0[6], a1[6];
        #pragma unroll
        for (int c = 0; c < 6; c++) {
            a0[c] = make_float4(0.f, 0.f, 0.f, 0.f);
            a1[c] = make_float4(0.f, 0.f, 0.f, 0.f);
        }
        #pragma unroll
        for (int jj = 0; jj < 16; jj++) {
            int j = jj * 32 + lane;
            const float* vp = vs + j * KST;
            float p0 = e0[jj], p1 = e1[jj];
            #pragma unroll
            for (int c = 0; c < 6; c++) {
                float4 vv = *(const float4*)(vp + c * 4);
                a0[c].x += p0 * vv.x; a0[c].y += p0 * vv.y;
                a0[c].z += p0 * vv.z; a0[c].w += p0 * vv.w;
                a1[c].x += p1 * vv.x; a1[c].y += p1 * vv.y;
                a1[c].z += p1 * vv.z; a1[c].w += p1 * vv.w;
            }
        }
        float* wb = wbuf + warp * 48;
        #pragma unroll
        for (int c = 0; c < 6; c++) {
            float v0x = a0[c].x, v0y = a0[c].y, v0z = a0[c].z, v0w = a0[c].w;
            float v1x = a1[c].x, v1y = a1[c].y, v1z = a1[c].z, v1w = a1[c].w;
            #pragma unroll
            for (int o = 16; o > 0; o >>= 1) {
                v0x += __shfl_xor_sync(0xFFFFFFFFu, v0x, o);
                v0y += __shfl_xor_sync(0xFFFFFFFFu, v0y, o);
                v0z += __shfl_xor_sync(0xFFFFFFFFu, v0z, o);
                v0w += __shfl_xor_sync(0xFFFFFFFFu, v0w, o);
                v1x += __shfl_xor_sync(0xFFFFFFFFu, v1x, o);
                v1y += __shfl_xor_sync(0xFFFFFFFFu, v1y, o);
                v1z += __shfl_xor_sync(0xFFFFFFFFu, v1z, o);
                v1w += __shfl_xor_sync(0xFFFFFFFFu, v1w, o);
            }
            if (lane == 0) {
                wb[c * 4 + 0] = v0x; wb[c * 4 + 1] = v0y;
                wb[c * 4 + 2] = v0z; wb[c * 4 + 3] = v0w;
                wb[24 + c * 4 + 0] = v1x; wb[24 + c * 4 + 1] = v1y;
                wb[24 + c * 4 + 2] = v1z; wb[24 + c * 4 + 3] = v1w;
            }
        }
        __syncwarp();
        if (lane < 24) {
            float ov0 = wb[lane] * inv0;
            float gv0 = g_qkvg[qrow0 * (4 * CS) + 3 * CS + h * HD + lane];
            g_att[qrow0 * CS + h * HD + lane] = ov0 * gv0;
            float ov1 = wb[24 + lane] * inv1;
            float gv1 = g_qkvg[qrow1 * (4 * CS) + 3 * CS + h * HD + lane];
            g_att[qrow1 * CS + h * HD + lane] = ov1 * gv1;
        }
        __syncwarp();
    }
}

// ---------------- K4: output projection — k-split x4, atomic accumulate ----------------
// grid (6, 8, 4): z = k-quarter (96 deep). out pre-initialized with bo in prep_ln.
__global__ void outproj_kernel(const float* __restrict__ Wo, float* __restrict__ out) {
    __shared__ float As[16][64];
    __shared__ float Bs[16][68];
    int bm = blockIdx.y * 64, bn = blockIdx.x * 64;
    int kbase = blockIdx.z * 96;
    int tid = threadIdx.x;
    int tx = tid & 15, ty = tid >> 4;
    int arow = tid >> 2, acol4 = (tid & 3) * 4;
    int brow = tid >> 4, bcol4 = (tid & 15) * 4;
    float acc[4][4] = {};

    for (int k0 = kbase; k0 < kbase + 96; k0 += 16) {
        float4 av = *(const float4*)(g_att + (bm + arow) * CS + k0 + acol4);
        As[acol4 + 0][arow] = av.x;
        As[acol4 + 1][arow] = av.y;
        As[acol4 + 2][arow] = av.z;
        As[acol4 + 3][arow] = av.w;
        float4 bv = *(const float4*)(Wo + (k0 + brow) * CS + bn + bcol4);
        *(float4*)&Bs[brow][bcol4] = bv;
        __syncthreads();
        #pragma unroll
        for (int kk = 0; kk < 16; kk++) {
            float4 a4 = *(const float4*)&As[kk][ty * 4];
            float4 b4 = *(const float4*)&Bs[kk][tx * 4];
            float af[4] = {a4.x, a4.y, a4.z, a4.w};
            float bf[4] = {b4.x, b4.y, b4.z, b4.w};
            #pragma unroll
            for (int i = 0; i < 4; i++)
                #pragma unroll
                for (int j = 0; j < 4; j++)
                    acc[i][j] += af[i] * bf[j];
        }
        __syncthreads();
    }
    #pragma unroll
    for (int i = 0; i < 4; i++) {
        int row = bm + ty * 4 + i;
        float* o = out + row * CS + bn + tx * 4;
        #pragma unroll
        for (int j = 0; j < 4; j++)
            atomicAdd(&o[j], acc[i][j]);
    }
}

// ---------------- launch ----------------
extern "C" void kernel_launch(void* const* d_in, const int* in_sizes, int n_in,
                              void* d_out, int out_size) {
    (void)in_sizes; (void)n_in; (void)out_size;
    const float* a   = (const float*)d_in[0];
    const float* z   = (const float*)d_in[1];
    const float* g_a = (const float*)d_in[2];
    const float* b_a = (const float*)d_in[3];
    const float* g_z = (const float*)d_in[4];
    const float* b_z = (const float*)d_in[5];
    const float* Wz  = (const float*)d_in[6];
    const float* bz  = (const float*)d_in[7];
    const float* Wq  = (const float*)d_in[8];
    const float* Wk  = (const float*)d_in[9];
    const float* Wv  = (const float*)d_in[10];
    const float* Wg  = (const float*)d_in[11];
    const float* bg  = (const float*)d_in[12];
    const float* Wo  = (const float*)d_in[13];
    const float* bo  = (const float*)d_in[14];
    float* out = (float*)d_out;

    cudaFuncSetAttribute(fused_mid_kernel, cudaFuncAttributeMaxDynamicSharedMemorySize, PB_SMEM_BYTES);
    cudaFuncSetAttribute(attn_kernel, cudaFuncAttributeMaxDynamicSharedMemorySize, ATTN_SMEM_BYTES);

    prep_ln_kernel<<<NN + 1, 128>>>(a, g_a, b_a, g_z, b_z, Wz, bz, bo, out);
    fused_mid_kernel<<<192 + 2048, 256, PB_SMEM_BYTES>>>(z, Wq, Wk, Wv, Wg, bg);
    attn_kernel<<<dim3(8, 16), 256, ATTN_SMEM_BYTES>>>();
    outproj_kernel<<<dim3(6, 8, 4), 256>>>(Wo, out);
}

// round 14
// speedup vs baseline: 1.5385x; 1.0344x over previous
#include <cuda_runtime.h>
#include <math.h>

#define NN 512
#define CS 384
#define CZ 128
#define NH 16
#define HD 24
#define EPS 1e-5f
#define ZST 132   // padded z row stride; 16B-aligned, (ZST/4)%8==1 -> LDS.128 conflict-free
#define KST 28    // padded K/V row stride; 16B-aligned -> LDS.128 conflict-free

typedef unsigned long long u64;

// packed f32x2 FMA: d = a*b + d (elementwise on 2 packed floats)
#define FFMA2(d, a, b) asm("fma.rn.f32x2 %0, %1, %2, %0;" : "+l"(d) : "l"(a), "l"(b))
// broadcast one float into both lanes of a f32x2
#define PACK2(d, f) asm("mov.b64 %0, {%1, %1};" : "=l"(d) : "r"(__float_as_uint(f)))

__device__ __forceinline__ float u64lo(u64 v) { return __uint_as_float((unsigned)v); }
__device__ __forceinline__ float u64hi(u64 v) { return __uint_as_float((unsigned)(v >> 32)); }

// pair_bias smem layout (floats)
#define PB_ZS     (128 * ZST)
#define PB_WS     (NH * CZ)
#define PB_STATS  (256)
#define PB_PART   (4 * 32 * 17)
#define PB_SMEM_FLOATS (PB_ZS + PB_WS + PB_STATS + PB_PART)
#define PB_SMEM_BYTES  (PB_SMEM_FLOATS * 4)   // 85504

// attn smem: ks(512*28) + vs(512*28) + qs(64*28) + wbuf(8*48)
#define ATTN_SMEM_FLOATS (512 * KST * 2 + 64 * KST + 8 * 48)
#define ATTN_SMEM_BYTES  (ATTN_SMEM_FLOATS * 4)   // 123392

// ---------------- scratch ----------------
__device__ float g_an[NN * CS];
__device__ float g_qkvg[NN * 4 * CS];          // [q(pre-scaled) | k | v | g(sigmoid)]
__device__ float g_bias[(size_t)NH * NN * NN]; // [h][i][j]
__device__ float g_att[NN * CS];
__device__ float g_gwT[NH * CZ];
__device__ float g_colsum[NH];
__device__ float g_cconst[NH];

// ---------------- K1: fused prep (block 512) + LN(a) + out=bias init ----------------
__global__ void prep_ln_kernel(const float* __restrict__ a, const float* __restrict__ ga,
                               const float* __restrict__ ba,
                               const float* __restrict__ gz, const float* __restrict__ bzln,
                               const float* __restrict__ Wz, const float* __restrict__ bz,
                               const float* __restrict__ bo, float* __restrict__ out) {
    if (blockIdx.x == NN) {
        int c = threadIdx.x;  // 128
        float g = gz[c];
        #pragma unroll
        for (int h = 0; h < NH; h++) g_gwT[h * CZ + c] = g * Wz[c * NH + h];
        __syncthreads();
        if (c < NH) {
            float cs = 0.f, ct = bz[c];
            for (int k = 0; k < CZ; k++) {
                cs += g_gwT[c * CZ + k];
                ct += bzln[k] * Wz[k * NH + c];
            }
            g_colsum[c] = cs;
            g_cconst[c] = ct;
        }
        return;
    }
    int row = blockIdx.x, t = threadIdx.x;  // 128 threads
    const float* x = a + row * CS;
    float v0 = x[t], v1 = x[t + 128], v2 = x[t + 256];
    float s = v0 + v1 + v2;
    float q = v0 * v0 + v1 * v1 + v2 * v2;
    __shared__ float rs[4], rq[4];
    #pragma unroll
    for (int o = 16; o > 0; o >>= 1) {
        s += __shfl_xor_sync(0xFFFFFFFFu, s, o);
        q += __shfl_xor_sync(0xFFFFFFFFu, q, o);
    }
    if ((t & 31) == 0) { rs[t >> 5] = s; rq[t >> 5] = q; }
    __syncthreads();
    float S = rs[0] + rs[1] + rs[2] + rs[3];
    float Q = rq[0] + rq[1] + rq[2] + rq[3];
    float m = S * (1.f / CS);
    float var = Q * (1.f / CS) - m * m;
    float r = rsqrtf(var + EPS);
    float* o = g_an + row * CS;
    o[t]       = (v0 - m) * r * ga[t]       + ba[t];
    o[t + 128] = (v1 - m) * r * ga[t + 128] + ba[t + 128];
    o[t + 256] = (v2 - m) * r * ga[t + 256] + ba[t + 256];
    float* orow = out + row * CS;
    orow[t]       = bo[t];
    orow[t + 128] = bo[t + 128];
    orow[t + 256] = bo[t + 256];
}

// ---------------- qkvg role body ----------------
__device__ __forceinline__ void qkvg_body(float* smem, int mat, int bm, int bn,
                                          const float* __restrict__ Wq, const float* __restrict__ Wk,
                                          const float* __restrict__ Wv, const float* __restrict__ Wg,
                                          const float* __restrict__ bg) {
    float* As = smem;              // [16][64]
    float* Bs = smem + 16 * 64;    // [16][68]
    const float* B = (mat == 0) ? Wq : (mat == 1) ? Wk : (mat == 2) ? Wv : Wg;
    int tid = threadIdx.x;         // 256
    int tx = tid & 15, ty = tid >> 4;
    int arow = tid >> 2, acol4 = (tid & 3) * 4;
    int brow = tid >> 4, bcol4 = (tid & 15) * 4;
    float acc[4][4] = {};

    for (int k0 = 0; k0 < CS; k0 += 16) {
        float4 av = *(const float4*)(g_an + (bm + arow) * CS + k0 + acol4);
        As[(acol4 + 0) * 64 + arow] = av.x;
        As[(acol4 + 1) * 64 + arow] = av.y;
        As[(acol4 + 2) * 64 + arow] = av.z;
        As[(acol4 + 3) * 64 + arow] = av.w;
        float4 bv = *(const float4*)(B + (k0 + brow) * CS + bn + bcol4);
        *(float4*)&Bs[brow * 68 + bcol4] = bv;
        __syncthreads();
        #pragma unroll
        for (int kk = 0; kk < 16; kk++) {
            float4 a4 = *(const float4*)&As[kk * 64 + ty * 4];
            float4 b4 = *(const float4*)&Bs[kk * 68 + tx * 4];
            float af[4] = {a4.x, a4.y, a4.z, a4.w};
            float bf[4] = {b4.x, b4.y, b4.z, b4.w};
            #pragma unroll
            for (int i = 0; i < 4; i++)
                #pragma unroll
                for (int j = 0; j < 4; j++)
                    acc[i][j] += af[i] * bf[j];
        }
        __syncthreads();
    }
    int colbase = mat * CS + bn + tx * 4;
    #pragma unroll
    for (int i = 0; i < 4; i++) {
        int row = bm + ty * 4 + i;
        float* out = g_qkvg + row * (4 * CS) + colbase;
        #pragma unroll
        for (int j = 0; j < 4; j++) {
            float v = acc[i][j];
            if (mat == 0) v *= 0.2041241452319315f;  // 1/sqrt(24)
            else if (mat == 3) v = 1.f / (1.f + __expf(-(v + bg[bn + tx * 4 + j])));
            out[j] = v;
        }
    }
}

// ---------------- pair_bias role body (f32x2 packed compute) ----------------
__device__ __forceinline__ void pair_bias_body(float* smem, const float* __restrict__ z,
                                               int i, int j0) {
    float* zs    = smem;                 // 128 x ZST
    float* ws    = zs + PB_ZS;           // 16 x 128
    float* smean = ws + PB_WS;           // 128
    float* srstd = smean + 128;          // 128
    float* part  = srstd + 128;          // [4 hq][32 lane][17]
    __shared__ float cs_s[NH], cc_s[NH];

    int t = threadIdx.x;                 // 256
    int lane = t & 31, warp = t >> 5;    // 8 warps

    #pragma unroll
    for (int k = 0; k < PB_WS / 256; k++) ws[t + 256 * k] = g_gwT[t + 256 * k];
    if (t < NH) { cs_s[t] = g_colsum[t]; cc_s[t] = g_cconst[t]; }

    const float4* src = (const float4*)(z + ((size_t)i * NN + j0) * CZ);
    #pragma unroll
    for (int k = 0; k < 16; k++) {
        int idx = t + 256 * k;
        int row = idx >> 5, c4 = idx & 31;
        *(float4*)(zs + row * ZST + c4 * 4) = src[idx];
    }
    __syncthreads();

    {
        int row = t >> 1, half = t & 1;
        const float* zr = zs + row * ZST + half * 64;
        float s0 = 0, s1 = 0, s2 = 0, s3 = 0;
        float q0 = 0, q1 = 0, q2 = 0, q3 = 0;
        #pragma unroll
        for (int c = 0; c < 64; c += 4) {
            float4 v = *(const float4*)(zr + c);
            s0 += v.x; s1 += v.y; s2 += v.z; s3 += v.w;
            q0 += v.x * v.x; q1 += v.y * v.y; q2 += v.z * v.z; q3 += v.w * v.w;
        }
        float s = (s0 + s1) + (s2 + s3);
        float q = (q0 + q1) + (q2 + q3);
        s += __shfl_xor_sync(0xFFFFFFFFu, s, 1);
        q += __shfl_xor_sync(0xFFFFFFFFu, q, 1);
        if (half == 0) {
            float m = s * (1.f / 128.f);
            float var = q * (1.f / 128.f) - m * m;
            smean[row] = m;
            srstd[row] = rsqrtf(var + EPS);
        }
    }
    __syncthreads();

    int hq = warp & 3;
    int cbase = (warp >> 2) * 64;
    const float* z0 = zs + (lane +  0) * ZST + cbase;
    const float* z1 = zs + (lane + 32) * ZST + cbase;
    const float* z2 = zs + (lane + 64) * ZST + cbase;
    const float* z3 = zs + (lane + 96) * ZST + cbase;
    const float* w0 = ws + (hq * 4 + 0) * CZ + cbase;
    const float* w1 = ws + (hq * 4 + 1) * CZ + cbase;
    const float* w2 = ws + (hq * 4 + 2) * CZ + cbase;
    const float* w3 = ws + (hq * 4 + 3) * CZ + cbase;
    u64 acc2[4][4] = {};
    #pragma unroll 4
    for (int c = 0; c < 64; c += 4) {
        ulonglong2 zp[4], wp[4];
        zp[0] = *(const ulonglong2*)(z0 + c);
        zp[1] = *(const ulonglong2*)(z1 + c);
        zp[2] = *(const ulonglong2*)(z2 + c);
        zp[3] = *(const ulonglong2*)(z3 + c);
        wp[0] = *(const ulonglong2*)(w0 + c);
        wp[1] = *(const ulonglong2*)(w1 + c);
        wp[2] = *(const ulonglong2*)(w2 + c);
        wp[3] = *(const ulonglong2*)(w3 + c);
        #pragma unroll
        for (int r = 0; r < 4; r++)
            #pragma unroll
            for (int h = 0; h < 4; h++) {
                FFMA2(acc2[r][h], zp[r].x, wp[h].x);
                FFMA2(acc2[r][h], zp[r].y, wp[h].y);
            }
    }
    float acc[4][4];
    #pragma unroll
    for (int r = 0; r < 4; r++)
        #pragma unroll
        for (int h = 0; h < 4; h++)
            acc[r][h] = u64lo(acc2[r][h]) + u64hi(acc2[r][h]);

    if (warp >= 4) {
        float* p = part + (hq * 32 + lane) * 17;
        #pragma unroll
        for (int r = 0; r < 4; r++)
            #pragma unroll
            for (int h = 0; h < 4; h++)
                p[r * 4 + h] = acc[r][h];
    }
    __syncthreads();
    if (warp < 4) {
        const float* p = part + (hq * 32 + lane) * 17;
        #pragma unroll
        for (int rr = 0; rr < 4; rr++) {
            int row = lane + rr * 32;
            float m = smean[row], r = srstd[row];
            #pragma unroll
            for (int hh = 0; hh < 4; hh++) {
                int h = hq * 4 + hh;
                float v = acc[rr][hh] + p[rr * 4 + hh];
                g_bias[((size_t)h * NN + i) * NN + j0 + row] =
                    r * (v - m * cs_s[h]) + cc_s[h];
            }
        }
    }
}

// ---------------- K2: merged pair_bias + qkvg ----------------
__global__ void __launch_bounds__(256) fused_mid_kernel(
    const float* __restrict__ z,
    const float* __restrict__ Wq, const float* __restrict__ Wk,
    const float* __restrict__ Wv, const float* __restrict__ Wg,
    const float* __restrict__ bg) {
    extern __shared__ float smem[];
    if (blockIdx.x < 192) {
        int b = blockIdx.x;
        int mat = b / 48;
        int rem = b - mat * 48;
        int bx = rem % 6, by = rem / 6;
        qkvg_body(smem, mat, by * 64, bx * 64, Wq, Wk, Wv, Wg, bg);
    } else {
        int pb = blockIdx.x - 192;   // 0..2047
        int i = pb >> 2;
        int j0 = (pb & 3) * 128;
        pair_bias_body(smem, z, i, j0);
    }
}

// ---------------- K3: attention — f32x2 packed QK/PV, shuffle reductions ----------------
__global__ void attn_kernel() {
    extern __shared__ float smem[];
    float* ks   = smem;                  // 512 x 28
    float* vs   = ks + 512 * KST;        // 512 x 28
    float* qs   = vs + 512 * KST;        // 64 x 28
    float* wbuf = qs + 64 * KST;         // 8 x 48

    int h  = blockIdx.y;
    int q0 = blockIdx.x * 64;
    int tid = threadIdx.x, lane = tid & 31, warp = tid >> 5;

    for (int idx = tid; idx < 512 * 24; idx += 256) {
        int n = idx / 24, d = idx - n * 24;
        const float* row = g_qkvg + n * (4 * CS);
        ks[n * KST + d] = row[CS + h * HD + d];
        vs[n * KST + d] = row[2 * CS + h * HD + d];
    }
    for (int idx = tid; idx < 64 * 24; idx += 256) {
        int n = idx / 24, d = idx - n * 24;
        qs[n * KST + d] = g_qkvg[(q0 + n) * (4 * CS) + h * HD + d];
    }
    __syncthreads();

    for (int qp2 = 0; qp2 < 4; qp2++) {
        int r0 = warp * 8 + qp2 * 2;
        int qrow0 = q0 + r0, qrow1 = qrow0 + 1;

        // q rows packed: 24 floats = 6 ulonglong2 each
        ulonglong2 qa2[6], qb2[6];
        #pragma unroll
        for (int c = 0; c < 6; c++) {
            qa2[c] = *(const ulonglong2*)(qs + r0 * KST + c * 4);
            qb2[c] = *(const ulonglong2*)(qs + (r0 + 1) * KST + c * 4);
        }
        const float* brow0 = g_bias + ((size_t)h * NN + qrow0) * NN;
        const float* brow1 = g_bias + ((size_t)h * NN + qrow1) * NN;

        float e0[16], e1[16];
        float mx0 = -1e30f, mx1 = -1e30f;
        #pragma unroll
        for (int jj = 0; jj < 16; jj++) {
            int j = jj * 32 + lane;
            const ulonglong2* kp2 = (const ulonglong2*)(ks + j * KST);
            u64 s0a = 0, s0b = 0, s1a = 0, s1b = 0;
            #pragma unroll
            for (int c = 0; c < 6; c++) {
                ulonglong2 kv = kp2[c];
                if (c & 1) {
                    FFMA2(s0b, qa2[c].x, kv.x); FFMA2(s0b, qa2[c].y, kv.y);
                    FFMA2(s1b, qb2[c].x, kv.x); FFMA2(s1b, qb2[c].y, kv.y);
                } else {
                    FFMA2(s0a, qa2[c].x, kv.x); FFMA2(s0a, qa2[c].y, kv.y);
                    FFMA2(s1a, qb2[c].x, kv.x); FFMA2(s1a, qb2[c].y, kv.y);
                }
            }
            float s0 = (u64lo(s0a) + u64hi(s0a)) + (u64lo(s0b) + u64hi(s0b)) + brow0[j];
            float s1 = (u64lo(s1a) + u64hi(s1a)) + (u64lo(s1b) + u64hi(s1b)) + brow1[j];
            e0[jj] = s0; e1[jj] = s1;
            mx0 = fmaxf(mx0, s0); mx1 = fmaxf(mx1, s1);
        }
        #pragma unroll
        for (int o = 16; o > 0; o >>= 1) {
            mx0 = fmaxf(mx0, __shfl_xor_sync(0xFFFFFFFFu, mx0, o));
            mx1 = fmaxf(mx1, __shfl_xor_sync(0xFFFFFFFFu, mx1, o));
        }
        float sum0 = 0.f, sum1 = 0.f;
        #pragma unroll
        for (int jj = 0; jj < 16; jj++) {
            e0[jj] = __expf(e0[jj] - mx0); sum0 += e0[jj];
            e1[jj] = __expf(e1[jj] - mx1); sum1 += e1[jj];
        }
        #pragma unroll
        for (int o = 16; o > 0; o >>= 1) {
            sum0 += __shfl_xor_sync(0xFFFFFFFFu, sum0, o);
            sum1 += __shfl_xor_sync(0xFFFFFFFFu, sum1, o);
        }
        float inv0 = 1.f / sum0, inv1 = 1.f / sum1;

        // PV: packed accumulators, 24 floats per row = 12 u64
        u64 a0p[12] = {}, a1p[12] = {};
        #pragma unroll
        for (int jj = 0; jj < 16; jj++) {
            int j = jj * 32 + lane;
            const ulonglong2* vp2 = (const ulonglong2*)(vs + j * KST);
            u64 p0p, p1p;
            PACK2(p0p, e0[jj]);
            PACK2(p1p, e1[jj]);
            #pragma unroll
            for (int c = 0; c < 6; c++) {
                ulonglong2 vv = vp2[c];
                FFMA2(a0p[2 * c], p0p, vv.x); FFMA2(a0p[2 * c + 1], p0p, vv.y);
                FFMA2(a1p[2 * c], p1p, vv.x); FFMA2(a1p[2 * c + 1], p1p, vv.y);
            }
        }
        // shuffle lane-reduce on packed u64 halves (4 values per step via 2 u64 shuffles)
        float* wb = wbuf + warp * 48;
        #pragma unroll
        for (int m = 0; m < 12; m++) {
            float l0 = u64lo(a0p[m]), h0 = u64hi(a0p[m]);
            float l1 = u64lo(a1p[m]), h1 = u64hi(a1p[m]);
            #pragma unroll
            for (int o = 16; o > 0; o >>= 1) {
                l0 += __shfl_xor_sync(0xFFFFFFFFu, l0, o);
                h0 += __shfl_xor_sync(0xFFFFFFFFu, h0, o);
                l1 += __shfl_xor_sync(0xFFFFFFFFu, l1, o);
                h1 += __shfl_xor_sync(0xFFFFFFFFu, h1, o);
            }
            if (lane == 0) {
                wb[2 * m] = l0; wb[2 * m + 1] = h0;
                wb[24 + 2 * m] = l1; wb[24 + 2 * m + 1] = h1;
            }
        }
        __syncwarp();
        if (lane < 24) {
            float ov0 = wb[lane] * inv0;
            float gv0 = g_qkvg[qrow0 * (4 * CS) + 3 * CS + h * HD + lane];
            g_att[qrow0 * CS + h * HD + lane] = ov0 * gv0;
            float ov1 = wb[24 + lane] * inv1;
            float gv1 = g_qkvg[qrow1 * (4 * CS) + 3 * CS + h * HD + lane];
            g_att[qrow1 * CS + h * HD + lane] = ov1 * gv1;
        }
        __syncwarp();
    }
}

// ---------------- K4: output projection — k-split x8, atomic accumulate ----------------
__global__ void outproj_kernel(const float* __restrict__ Wo, float* __restrict__ out) {
    __shared__ float As[16][64];
    __shared__ float Bs[16][68];
    int bm = blockIdx.y * 64, bn = blockIdx.x * 64;
    int kbase = blockIdx.z * 48;
    int tid = threadIdx.x;
    int tx = tid & 15, ty = tid >> 4;
    int arow = tid >> 2, acol4 = (tid & 3) * 4;
    int brow = tid >> 4, bcol4 = (tid & 15) * 4;
    float acc[4][4] = {};

    for (int k0 = kbase; k0 < kbase + 48; k0 += 16) {
        float4 av = *(const float4*)(g_att + (bm + arow) * CS + k0 + acol4);
        As[acol4 + 0][arow] = av.x;
        As[acol4 + 1][arow] = av.y;
        As[acol4 + 2][arow] = av.z;
        As[acol4 + 3][arow] = av.w;
        float4 bv = *(const float4*)(Wo + (k0 + brow) * CS + bn + bcol4);
        *(float4*)&Bs[brow][bcol4] = bv;
        __syncthreads();
        #pragma unroll
        for (int kk = 0; kk < 16; kk++) {
            float4 a4 = *(const float4*)&As[kk][ty * 4];
            float4 b4 = *(const float4*)&Bs[kk][tx * 4];
            float af[4] = {a4.x, a4.y, a4.z, a4.w};
            float bf[4] = {b4.x, b4.y, b4.z, b4.w};
            #pragma unroll
            for (int i = 0; i < 4; i++)
                #pragma unroll
                for (int j = 0; j < 4; j++)
                    acc[i][j] += af[i] * bf[j];
        }
        __syncthreads();
    }
    #pragma unroll
    for (int i = 0; i < 4; i++) {
        int row = bm + ty * 4 + i;
        float* o = out + row * CS + bn + tx * 4;
        #pragma unroll
        for (int j = 0; j < 4; j++)
            atomicAdd(&o[j], acc[i][j]);
    }
}

// ---------------- launch ----------------
extern "C" void kernel_launch(void* const* d_in, const int* in_sizes, int n_in,
                              void* d_out, int out_size) {
    (void)in_sizes; (void)n_in; (void)out_size;
    const float* a   = (const float*)d_in[0];
    const float* z   = (const float*)d_in[1];
    const float* g_a = (const float*)d_in[2];
    const float* b_a = (const float*)d_in[3];
    const float* g_z = (const float*)d_in[4];
    const float* b_z = (const float*)d_in[5];
    const float* Wz  = (const float*)d_in[6];
    const float* bz  = (const float*)d_in[7];
    const float* Wq  = (const float*)d_in[8];
    const float* Wk  = (const float*)d_in[9];
    const float* Wv  = (const float*)d_in[10];
    const float* Wg  = (const float*)d_in[11];
    const float* bg  = (const float*)d_in[12];
    const float* Wo  = (const float*)d_in[13];
    const float* bo  = (const float*)d_in[14];
    float* out = (float*)d_out;

    cudaFuncSetAttribute(fused_mid_kernel, cudaFuncAttributeMaxDynamicSharedMemorySize, PB_SMEM_BYTES);
    cudaFuncSetAttribute(attn_kernel, cudaFuncAttributeMaxDynamicSharedMemorySize, ATTN_SMEM_BYTES);

    prep_ln_kernel<<<NN + 1, 128>>>(a, g_a, b_a, g_z, b_z, Wz, bz, bo, out);
    fused_mid_kernel<<<192 + 2048, 256, PB_SMEM_BYTES>>>(z, Wq, Wk, Wv, Wg, bg);
    attn_kernel<<<dim3(8, 16), 256, ATTN_SMEM_BYTES>>>();
    outproj_kernel<<<dim3(6, 8, 8), 256>>>(Wo, out);
}